// round 1
// baseline (speedup 1.0000x reference)
#include <cuda_runtime.h>
#include <math.h>
#include <stdint.h>

#define Bdim  4
#define Sdim  2048
#define Ddim  2048
#define Edim  8
#define HDdim 256
#define F3    768
#define KMAXd 2048
#define EB    (Edim*Bdim)

// ---------------- scratch (device globals; no allocations allowed) ----------
__device__ float g_qkv[(size_t)EB * KMAXd * F3];   // per (e,b,k): [qf(256)|kf(256)|v(256)] after rope
__device__ float g_ctx[(size_t)EB * KMAXd * HDdim];
__device__ int   g_sid[EB * KMAXd];
__device__ int   g_cnt[EB];
__device__ int   g_maxlen;
__device__ unsigned char g_emask[Bdim * Sdim];

// ---------------- 1) gate logits + top-2 expert mask ------------------------
__global__ void k_gate(const float* __restrict__ X,
                       const float* __restrict__ wg,
                       const float* __restrict__ bg)
{
    int bs = blockIdx.x;                     // b*S + s
    const float* xr = X + (size_t)bs * Ddim;
    double acc[8];
#pragma unroll
    for (int e = 0; e < 8; e++) acc[e] = 0.0;
    for (int d = threadIdx.x; d < Ddim; d += 128) {
        float xv = xr[d];
        const float* w = wg + d * Edim;
#pragma unroll
        for (int e = 0; e < 8; e++) acc[e] += (double)xv * (double)w[e];
    }
#pragma unroll
    for (int e = 0; e < 8; e++)
#pragma unroll
        for (int off = 16; off; off >>= 1)
            acc[e] += __shfl_down_sync(0xffffffffu, acc[e], off);

    __shared__ double red[4][8];
    int wid = threadIdx.x >> 5, lane = threadIdx.x & 31;
    if (lane == 0) {
#pragma unroll
        for (int e = 0; e < 8; e++) red[wid][e] = acc[e];
    }
    __syncthreads();
    if (threadIdx.x == 0) {
        float v[8];
#pragma unroll
        for (int e = 0; e < 8; e++)
            v[e] = (float)(red[0][e] + red[1][e] + red[2][e] + red[3][e]) + bg[e];
        int e1 = 0; float b1 = v[0];
#pragma unroll
        for (int e = 1; e < 8; e++) if (v[e] > b1) { b1 = v[e]; e1 = e; }
        int e2 = -1; float b2 = -3.0e38f;
#pragma unroll
        for (int e = 0; e < 8; e++) if (e != e1 && v[e] > b2) { b2 = v[e]; e2 = e; }
        g_emask[bs] = (unsigned char)((1u << e1) | (1u << e2));
    }
}

__global__ void k_reset() { g_maxlen = 0; }

// ---------------- 2) per-(e,b) member counts + global max -------------------
__global__ void k_count()
{
    int eb = blockIdx.x; int e = eb / Bdim, b = eb % Bdim;
    int n = 0;
    for (int s = threadIdx.x; s < Sdim; s += 256)
        n += (g_emask[b * Sdim + s] >> e) & 1;
#pragma unroll
    for (int off = 16; off; off >>= 1) n += __shfl_down_sync(0xffffffffu, n, off);
    __shared__ int sm[8];
    int wid = threadIdx.x >> 5, lane = threadIdx.x & 31;
    if (lane == 0) sm[wid] = n;
    __syncthreads();
    if (threadIdx.x == 0) {
        int t = 0;
#pragma unroll
        for (int w = 0; w < 8; w++) t += sm[w];
        g_cnt[eb] = t;
        atomicMax(&g_maxlen, t);
    }
}

// ---------------- 3) build seq_ids: members + lowest-index zero padding -----
__global__ void k_build()
{
    int eb = blockIdx.x; int e = eb / Bdim, b = eb % Bdim;
    int pad = g_maxlen - g_cnt[eb];
    __shared__ int wsum[8];
    __shared__ int carry;
    if (threadIdx.x == 0) carry = 0;
    __syncthreads();
    int wid = threadIdx.x >> 5, lane = threadIdx.x & 31;
    for (int s0 = 0; s0 < Sdim; s0 += 256) {
        int s = s0 + threadIdx.x;
        int m = (g_emask[b * Sdim + s] >> e) & 1;
        unsigned bal = __ballot_sync(0xffffffffu, m);
        int mp_w = __popc(bal & ((1u << lane) - 1u));
        if (lane == 0) wsum[wid] = __popc(bal);
        __syncthreads();
        int pre = 0;
#pragma unroll
        for (int w = 0; w < 8; w++) if (w < wid) pre += wsum[w];
        int mp  = carry + pre + mp_w;     // members strictly before s
        int nmb = s - mp;                 // non-members strictly before s
        bool sel = m || (nmb < pad);
        int pos  = mp + min(nmb, pad);
        if (sel) g_sid[eb * KMAXd + pos] = s;
        __syncthreads();
        if (threadIdx.x == 0) {
            int t = 0;
#pragma unroll
            for (int w = 0; w < 8; w++) t += wsum[w];
            carry += t;
        }
        __syncthreads();
    }
}

// ---------------- 4) QKV GEMM: (K_len x 2048) @ (2048 x 768), gathered rows -
__global__ void __launch_bounds__(256) k_qkv(const float* __restrict__ X,
                                             const float* __restrict__ W,
                                             const float* __restrict__ bq)
{
    int K_len = g_maxlen;
    int row0 = blockIdx.y * 64; if (row0 >= K_len) return;
    int eb = blockIdx.z; int e = eb / Bdim, b = eb % Bdim;
    int col0 = blockIdx.x * 64;

    __shared__ float As[16][68];
    __shared__ float Bs[16][68];
    __shared__ int   sids[64];
    int tid = threadIdx.x;
    if (tid < 64) {
        int r = row0 + tid;
        sids[tid] = g_sid[eb * KMAXd + min(r, K_len - 1)];
    }
    __syncthreads();

    float acc[4][4];
#pragma unroll
    for (int i = 0; i < 4; i++)
#pragma unroll
        for (int j = 0; j < 4; j++) acc[i][j] = 0.f;

    int ty = tid >> 4, tx = tid & 15;
    const float* Wb = W + (size_t)e * Ddim * F3;

    for (int d0 = 0; d0 < Ddim; d0 += 16) {
#pragma unroll
        for (int j = 0; j < 4; j++) {
            int li = tid + j * 256;
            int m = li >> 4, dd = li & 15;
            As[dd][m] = X[((size_t)b * Sdim + sids[m]) * Ddim + d0 + dd];
            int dd2 = li >> 6, n2 = li & 63;
            Bs[dd2][n2] = Wb[(size_t)(d0 + dd2) * F3 + col0 + n2];
        }
        __syncthreads();
#pragma unroll
        for (int dd = 0; dd < 16; dd++) {
            float4 av = *reinterpret_cast<const float4*>(&As[dd][ty * 4]);
            float4 bv = *reinterpret_cast<const float4*>(&Bs[dd][tx * 4]);
            float aa[4] = {av.x, av.y, av.z, av.w};
            float bb[4] = {bv.x, bv.y, bv.z, bv.w};
#pragma unroll
            for (int i = 0; i < 4; i++)
#pragma unroll
                for (int j = 0; j < 4; j++) acc[i][j] += aa[i] * bb[j];
        }
        __syncthreads();
    }
#pragma unroll
    for (int i = 0; i < 4; i++) {
        int r = row0 + ty * 4 + i;
        if (r < K_len) {
            float* op = g_qkv + ((size_t)eb * KMAXd + r) * F3 + col0 + tx * 4;
            const float* bp = bq + e * F3 + col0 + tx * 4;
#pragma unroll
            for (int j = 0; j < 4; j++) op[j] = acc[i][j] + bp[j];
        }
    }
}

// ---------------- 5) RoPE (in-place): row -> [rope(pe)|nope] for q and k ----
__global__ void k_rope()
{
    int k = blockIdx.x;
    if (k >= g_maxlen) return;
    int eb = blockIdx.y;
    int e = eb / Bdim;
    int tid = threadIdx.x;          // 128 = 2 comps * 64 pairs
    int comp = tid >> 6;            // 0: q, 1: k
    int i = tid & 63;
    double j2 = (double)(2 * (e * 64 + i));
    double freq = exp(-(j2 / 1024.0) * log(10000.0));
    float freqf = (float)freq;
    float angf  = (float)k * freqf;      // match numpy fp32 angle table
    double ss, cc;
    sincos((double)angf, &ss, &cc);
    float c = (float)cc, s = (float)ss;

    float* p = g_qkv + ((size_t)eb * KMAXd + k) * F3 + comp * 256;
    float a  = p[128 + 2 * i], bb = p[129 + 2 * i];
    float n0 = p[2 * i],       n1 = p[2 * i + 1];
    p[2 * i]       = a * c - bb * s;
    p[2 * i + 1]   = a * s + bb * c;
    p[128 + 2 * i] = n0;
    p[129 + 2 * i] = n1;
}

// ---------------- 6) attention: QTILE=4 per block, scores in smem -----------
__global__ void __launch_bounds__(256) k_attn(const float* __restrict__ mask)
{
    int K_len = g_maxlen;
    int q0 = blockIdx.x * 4; if (q0 >= K_len) return;
    int eb = blockIdx.y; int b = eb % Bdim;

    __shared__ float sq[4][256];
    __shared__ float sc[4][KMAXd];
    __shared__ float sred[8];

    int tid = threadIdx.x;
    const float* base = g_qkv + (size_t)eb * KMAXd * F3;
#pragma unroll
    for (int j = 0; j < 4; j++) {
        int q = q0 + j;
        sq[j][tid] = (q < K_len) ? base[(size_t)q * F3 + tid] : 0.f;
    }
    __syncthreads();

    int wid = tid >> 5, lane = tid & 31;
    for (int k = wid; k < K_len; k += 8) {
        const float* kr = base + (size_t)k * F3 + 256;
        float p0 = 0.f, p1 = 0.f, p2 = 0.f, p3 = 0.f;
#pragma unroll
        for (int jj = 0; jj < 8; jj++) {
            int c = lane + jj * 32;
            float kv = kr[c];
            p0 += kv * sq[0][c]; p1 += kv * sq[1][c];
            p2 += kv * sq[2][c]; p3 += kv * sq[3][c];
        }
#pragma unroll
        for (int off = 16; off; off >>= 1) {
            p0 += __shfl_down_sync(0xffffffffu, p0, off);
            p1 += __shfl_down_sync(0xffffffffu, p1, off);
            p2 += __shfl_down_sync(0xffffffffu, p2, off);
            p3 += __shfl_down_sync(0xffffffffu, p3, off);
        }
        if (lane == 0) {
            int sk = g_sid[eb * KMAXd + k];
            float mt = -1000000.0f * (1.0f - mask[b * Sdim + sk]);
            sc[0][k] = p0 * 0.0625f + mt;
            sc[1][k] = p1 * 0.0625f + mt;
            sc[2][k] = p2 * 0.0625f + mt;
            sc[3][k] = p3 * 0.0625f + mt;
        }
    }
    __syncthreads();

    float sinv[4];
    for (int j = 0; j < 4; j++) {
        float lm = -3.0e38f;
        for (int k = tid; k < K_len; k += 256) lm = fmaxf(lm, sc[j][k]);
#pragma unroll
        for (int off = 16; off; off >>= 1)
            lm = fmaxf(lm, __shfl_xor_sync(0xffffffffu, lm, off));
        if (lane == 0) sred[wid] = lm;
        __syncthreads();
        float m8 = sred[0];
#pragma unroll
        for (int w = 1; w < 8; w++) m8 = fmaxf(m8, sred[w]);
        __syncthreads();
        float ls = 0.f;
        for (int k = tid; k < K_len; k += 256) {
            float ev = expf(sc[j][k] - m8);
            sc[j][k] = ev;
            ls += ev;
        }
#pragma unroll
        for (int off = 16; off; off >>= 1)
            ls += __shfl_xor_sync(0xffffffffu, ls, off);
        if (lane == 0) sred[wid] = ls;
        __syncthreads();
        float s8 = 0.f;
#pragma unroll
        for (int w = 0; w < 8; w++) s8 += sred[w];
        sinv[j] = 1.0f / s8;
        __syncthreads();
    }

    // ctx = (P @ V); normalize at the end
    float a0 = 0.f, a1 = 0.f, a2 = 0.f, a3 = 0.f;
    const float* vb = base + 512 + tid;
#pragma unroll 8
    for (int k = 0; k < K_len; k++) {
        float vv = vb[(size_t)k * F3];
        a0 += sc[0][k] * vv; a1 += sc[1][k] * vv;
        a2 += sc[2][k] * vv; a3 += sc[3][k] * vv;
    }
    float* cb = g_ctx + ((size_t)eb * KMAXd + q0) * HDdim + tid;
    if (q0 + 0 < K_len) cb[0 * HDdim] = a0 * sinv[0];
    if (q0 + 1 < K_len) cb[1 * HDdim] = a1 * sinv[1];
    if (q0 + 2 < K_len) cb[2 * HDdim] = a2 * sinv[2];
    if (q0 + 3 < K_len) cb[3 * HDdim] = a3 * sinv[3];
}

// ---------------- 7) FF GEMM (K_len x 256)@(256 x 2048) + scatter-add -------
__global__ void __launch_bounds__(256) k_ff(const float* __restrict__ Wf,
                                            const float* __restrict__ bff,
                                            float* __restrict__ out)
{
    int K_len = g_maxlen;
    int row0 = blockIdx.y * 64; if (row0 >= K_len) return;
    int eb = blockIdx.z; int e = eb / Bdim, b = eb % Bdim;
    int col0 = blockIdx.x * 64;

    __shared__ float As[16][68];
    __shared__ float Bs[16][68];
    __shared__ int   sids[64];
    int tid = threadIdx.x;
    if (tid < 64) {
        int r = row0 + tid;
        sids[tid] = g_sid[eb * KMAXd + min(r, K_len - 1)];
    }

    float acc[4][4];
#pragma unroll
    for (int i = 0; i < 4; i++)
#pragma unroll
        for (int j = 0; j < 4; j++) acc[i][j] = 0.f;

    int ty = tid >> 4, tx = tid & 15;
    const float* Wb = Wf + (size_t)e * HDdim * Ddim;
    const float* Ab = g_ctx + (size_t)eb * KMAXd * HDdim;

    for (int d0 = 0; d0 < HDdim; d0 += 16) {
#pragma unroll
        for (int j = 0; j < 4; j++) {
            int li = tid + j * 256;
            int m = li >> 4, dd = li & 15;
            As[dd][m] = Ab[(size_t)(row0 + m) * HDdim + d0 + dd];
            int dd2 = li >> 6, n2 = li & 63;
            Bs[dd2][n2] = Wb[(size_t)(d0 + dd2) * Ddim + col0 + n2];
        }
        __syncthreads();
#pragma unroll
        for (int dd = 0; dd < 16; dd++) {
            float4 av = *reinterpret_cast<const float4*>(&As[dd][ty * 4]);
            float4 bv = *reinterpret_cast<const float4*>(&Bs[dd][tx * 4]);
            float aa[4] = {av.x, av.y, av.z, av.w};
            float bb[4] = {bv.x, bv.y, bv.z, bv.w};
#pragma unroll
            for (int i = 0; i < 4; i++)
#pragma unroll
                for (int j = 0; j < 4; j++) acc[i][j] += aa[i] * bb[j];
        }
        __syncthreads();
    }
#pragma unroll
    for (int i = 0; i < 4; i++) {
        int r = row0 + ty * 4 + i;
        if (r < K_len) {
            int sid = sids[ty * 4 + i];
            float* op = out + ((size_t)b * Sdim + sid) * Ddim + col0 + tx * 4;
            const float* bp = bff + col0 + tx * 4;
#pragma unroll
            for (int j = 0; j < 4; j++) atomicAdd(&op[j], acc[i][j] + bp[j]);
        }
    }
}

// ---------------- launch -----------------------------------------------------
extern "C" void kernel_launch(void* const* d_in, const int* in_sizes, int n_in,
                              void* d_out, int out_size)
{
    const float* X    = (const float*)d_in[0];
    const float* mask = (const float*)d_in[1];
    const float* wg   = (const float*)d_in[2];
    const float* bg   = (const float*)d_in[3];
    const float* Wqkv = (const float*)d_in[4];
    const float* bqkv = (const float*)d_in[5];
    const float* Wff  = (const float*)d_in[6];
    const float* bff  = (const float*)d_in[7];
    float* out = (float*)d_out;

    cudaMemsetAsync(out, 0, (size_t)out_size * sizeof(float));

    k_gate<<<Bdim * Sdim, 128>>>(X, wg, bg);
    k_reset<<<1, 1>>>();
    k_count<<<EB, 256>>>();
    k_build<<<EB, 256>>>();
    k_qkv<<<dim3(F3 / 64, Sdim / 64, EB), 256>>>(X, Wqkv, bqkv);
    k_rope<<<dim3(Sdim, EB), 128>>>();
    k_attn<<<dim3(Sdim / 4, EB), 256>>>(mask);
    k_ff<<<dim3(Ddim / 64, Sdim / 64, EB), 256>>>(Wff, bff, out);
}

// round 3
// speedup vs baseline: 1.4413x; 1.4413x over previous
#include <cuda_runtime.h>
#include <cuda_bf16.h>
#include <mma.h>
#include <math.h>
#include <stdint.h>

using namespace nvcuda;

#define Bdim  4
#define Sdim  2048
#define Ddim  2048
#define Edim  8
#define HDdim 256
#define F3    768
#define KMAXd 2048
#define EB    (Edim*Bdim)

typedef __nv_bfloat16 bf16;

// ---------------- scratch (device globals; no allocations allowed) ----------
__device__ float g_qkv[(size_t)EB * KMAXd * F3];   // per (e,b,k): [qf|kf|v] after rope
__device__ bf16  g_ctxh[(size_t)EB * KMAXd * HDdim];
__device__ bf16  g_ctxl[(size_t)EB * KMAXd * HDdim];
__device__ bf16  g_Xh[(size_t)Bdim * Sdim * Ddim];
__device__ bf16  g_Xl[(size_t)Bdim * Sdim * Ddim];
__device__ bf16  g_Wqh[(size_t)Edim * Ddim * F3];
__device__ bf16  g_Wql[(size_t)Edim * Ddim * F3];
__device__ bf16  g_Wfh[(size_t)Edim * HDdim * Ddim];
__device__ bf16  g_Wfl[(size_t)Edim * HDdim * Ddim];
__device__ int   g_sid[EB * KMAXd];
__device__ int   g_cnt[EB];
__device__ int   g_maxlen;
__device__ unsigned char g_emask[Bdim * Sdim];

// ---------------- 0) fp32 -> bf16 hi/lo split --------------------------------
__global__ void k_cvt(const float* __restrict__ src, bf16* __restrict__ h,
                      bf16* __restrict__ l, size_t n4)
{
    size_t i = (size_t)blockIdx.x * blockDim.x + threadIdx.x;
    if (i >= n4) return;
    float4 v = reinterpret_cast<const float4*>(src)[i];
    bf16 h0 = __float2bfloat16(v.x), h1 = __float2bfloat16(v.y);
    bf16 h2 = __float2bfloat16(v.z), h3 = __float2bfloat16(v.w);
    bf16 l0 = __float2bfloat16(v.x - __bfloat162float(h0));
    bf16 l1 = __float2bfloat16(v.y - __bfloat162float(h1));
    bf16 l2 = __float2bfloat16(v.z - __bfloat162float(h2));
    bf16 l3 = __float2bfloat16(v.w - __bfloat162float(h3));
    reinterpret_cast<ushort4*>(h)[i] = make_ushort4(__bfloat16_as_ushort(h0),
        __bfloat16_as_ushort(h1), __bfloat16_as_ushort(h2), __bfloat16_as_ushort(h3));
    reinterpret_cast<ushort4*>(l)[i] = make_ushort4(__bfloat16_as_ushort(l0),
        __bfloat16_as_ushort(l1), __bfloat16_as_ushort(l2), __bfloat16_as_ushort(l3));
}

// ---------------- 1) gate logits + top-2 expert mask ------------------------
__global__ void k_gate(const float* __restrict__ X,
                       const float* __restrict__ wg,
                       const float* __restrict__ bg)
{
    int bs = blockIdx.x;
    const float* xr = X + (size_t)bs * Ddim;
    double acc[8];
#pragma unroll
    for (int e = 0; e < 8; e++) acc[e] = 0.0;
    for (int d = threadIdx.x; d < Ddim; d += 128) {
        float xv = xr[d];
        const float* w = wg + d * Edim;
#pragma unroll
        for (int e = 0; e < 8; e++) acc[e] += (double)xv * (double)w[e];
    }
#pragma unroll
    for (int e = 0; e < 8; e++)
#pragma unroll
        for (int off = 16; off; off >>= 1)
            acc[e] += __shfl_down_sync(0xffffffffu, acc[e], off);

    __shared__ double red[4][8];
    int wid = threadIdx.x >> 5, lane = threadIdx.x & 31;
    if (lane == 0) {
#pragma unroll
        for (int e = 0; e < 8; e++) red[wid][e] = acc[e];
    }
    __syncthreads();
    if (threadIdx.x == 0) {
        float v[8];
#pragma unroll
        for (int e = 0; e < 8; e++)
            v[e] = (float)(red[0][e] + red[1][e] + red[2][e] + red[3][e]) + bg[e];
        int e1 = 0; float b1 = v[0];
#pragma unroll
        for (int e = 1; e < 8; e++) if (v[e] > b1) { b1 = v[e]; e1 = e; }
        int e2 = -1; float b2 = -3.0e38f;
#pragma unroll
        for (int e = 0; e < 8; e++) if (e != e1 && v[e] > b2) { b2 = v[e]; e2 = e; }
        g_emask[bs] = (unsigned char)((1u << e1) | (1u << e2));
    }
}

__global__ void k_reset() { g_maxlen = 0; }

// ---------------- 2) per-(e,b) member counts + global max -------------------
__global__ void k_count()
{
    int eb = blockIdx.x; int e = eb / Bdim, b = eb % Bdim;
    int n = 0;
    for (int s = threadIdx.x; s < Sdim; s += 256)
        n += (g_emask[b * Sdim + s] >> e) & 1;
#pragma unroll
    for (int off = 16; off; off >>= 1) n += __shfl_down_sync(0xffffffffu, n, off);
    __shared__ int sm[8];
    int wid = threadIdx.x >> 5, lane = threadIdx.x & 31;
    if (lane == 0) sm[wid] = n;
    __syncthreads();
    if (threadIdx.x == 0) {
        int t = 0;
#pragma unroll
        for (int w = 0; w < 8; w++) t += sm[w];
        g_cnt[eb] = t;
        atomicMax(&g_maxlen, t);
    }
}

// ---------------- 3) build seq_ids: members + lowest-index zero padding -----
__global__ void k_build()
{
    int eb = blockIdx.x; int e = eb / Bdim, b = eb % Bdim;
    int pad = g_maxlen - g_cnt[eb];
    __shared__ int wsum[8];
    __shared__ int carry;
    if (threadIdx.x == 0) carry = 0;
    __syncthreads();
    int wid = threadIdx.x >> 5, lane = threadIdx.x & 31;
    for (int s0 = 0; s0 < Sdim; s0 += 256) {
        int s = s0 + threadIdx.x;
        int m = (g_emask[b * Sdim + s] >> e) & 1;
        unsigned bal = __ballot_sync(0xffffffffu, m);
        int mp_w = __popc(bal & ((1u << lane) - 1u));
        if (lane == 0) wsum[wid] = __popc(bal);
        __syncthreads();
        int pre = 0;
#pragma unroll
        for (int w = 0; w < 8; w++) if (w < wid) pre += wsum[w];
        int mp  = carry + pre + mp_w;
        int nmb = s - mp;
        bool sel = m || (nmb < pad);
        int pos  = mp + min(nmb, pad);
        if (sel) g_sid[eb * KMAXd + pos] = s;
        __syncthreads();
        if (threadIdx.x == 0) {
            int t = 0;
#pragma unroll
            for (int w = 0; w < 8; w++) t += wsum[w];
            carry += t;
        }
        __syncthreads();
    }
}

// ---------------- 4) QKV GEMM via split-bf16 HMMA ----------------------------
// C[64 x 128] tile = gathered X rows @ W_qkv[e]; 3 mmas per product term.
// smem layout (bytes):
//   Ah @ 0      : 64*40*2  = 5120
//   Al @ 5120   : 5120
//   Bh @ 10240  : 32*136*2 = 8704
//   Bl @ 18944  : 8704   -> end 27648
//   Cs aliases @0: 64*132*4 = 33792  (epilogue only)
#define APITCH 40
#define BPITCH 136
#define CPITCH 132
#define SRAW_BYTES (64 * CPITCH * 4)

__global__ void __launch_bounds__(256) k_qkv_mma(const float* __restrict__ bq)
{
    int K_len = g_maxlen;
    int row0 = blockIdx.y * 64; if (row0 >= K_len) return;
    int eb = blockIdx.z; int e = eb / Bdim, b = eb % Bdim;
    int col0 = blockIdx.x * 128;

    __shared__ __align__(16) unsigned char sraw[SRAW_BYTES];
    __shared__ int sids[64];
    bf16* Ah = (bf16*)sraw;
    bf16* Al = (bf16*)(sraw + 5120);
    bf16* Bh = (bf16*)(sraw + 10240);
    bf16* Bl = (bf16*)(sraw + 18944);
    float* Cs = (float*)sraw;

    int tid = threadIdx.x;
    if (tid < 64) sids[tid] = g_sid[eb * KMAXd + min(row0 + tid, K_len - 1)];
    __syncthreads();

    int wid = tid >> 5;
    int wr = wid >> 2, wc = wid & 3;           // 2 x 4 warp grid

    wmma::fragment<wmma::accumulator, 16, 16, 16, float> acc[2][2];
#pragma unroll
    for (int i = 0; i < 2; i++)
#pragma unroll
        for (int j = 0; j < 2; j++) wmma::fill_fragment(acc[i][j], 0.f);

    const size_t xbase = (size_t)b * Sdim * Ddim;
    const size_t wbase = (size_t)e * Ddim * F3;

    for (int k0 = 0; k0 < Ddim; k0 += 32) {
        // A: 64 rows x 32 cols bf16 (hi+lo). 256 uint4 per matrix -> 1/thread.
        {
            int row = tid >> 2, c8 = (tid & 3) * 8;
            size_t src = xbase + (size_t)sids[row] * Ddim + k0 + c8;
            *(uint4*)&Ah[row * APITCH + c8] = *(const uint4*)&g_Xh[src];
            *(uint4*)&Al[row * APITCH + c8] = *(const uint4*)&g_Xl[src];
        }
        // B: 32 rows x 128 cols bf16 (hi+lo). 512 uint4 per matrix -> 2/thread.
#pragma unroll
        for (int it = 0; it < 2; it++) {
            int idx = tid + it * 256;
            int row = idx >> 4, c8 = (idx & 15) * 8;
            size_t src = wbase + (size_t)(k0 + row) * F3 + col0 + c8;
            *(uint4*)&Bh[row * BPITCH + c8] = *(const uint4*)&g_Wqh[src];
            *(uint4*)&Bl[row * BPITCH + c8] = *(const uint4*)&g_Wql[src];
        }
        __syncthreads();
#pragma unroll
        for (int kk = 0; kk < 32; kk += 16) {
            wmma::fragment<wmma::matrix_a, 16, 16, 16, bf16, wmma::row_major> ah[2], al[2];
            wmma::fragment<wmma::matrix_b, 16, 16, 16, bf16, wmma::row_major> bh[2], bl[2];
#pragma unroll
            for (int i = 0; i < 2; i++) {
                wmma::load_matrix_sync(ah[i], &Ah[(wr * 32 + i * 16) * APITCH + kk], APITCH);
                wmma::load_matrix_sync(al[i], &Al[(wr * 32 + i * 16) * APITCH + kk], APITCH);
            }
#pragma unroll
            for (int j = 0; j < 2; j++) {
                wmma::load_matrix_sync(bh[j], &Bh[kk * BPITCH + wc * 32 + j * 16], BPITCH);
                wmma::load_matrix_sync(bl[j], &Bl[kk * BPITCH + wc * 32 + j * 16], BPITCH);
            }
#pragma unroll
            for (int i = 0; i < 2; i++)
#pragma unroll
                for (int j = 0; j < 2; j++) {
                    wmma::mma_sync(acc[i][j], ah[i], bh[j], acc[i][j]);
                    wmma::mma_sync(acc[i][j], ah[i], bl[j], acc[i][j]);
                    wmma::mma_sync(acc[i][j], al[i], bh[j], acc[i][j]);
                }
        }
        __syncthreads();
    }
    // epilogue: stage to smem, add bias, store (all 64 rows; rows >= K_len unused)
#pragma unroll
    for (int i = 0; i < 2; i++)
#pragma unroll
        for (int j = 0; j < 2; j++)
            wmma::store_matrix_sync(&Cs[(wr * 32 + i * 16) * CPITCH + wc * 32 + j * 16],
                                    acc[i][j], CPITCH, wmma::mem_row_major);
    __syncthreads();
    for (int idx = tid; idx < 64 * 128; idx += 256) {
        int r = idx >> 7, c = idx & 127;
        g_qkv[((size_t)eb * KMAXd + row0 + r) * F3 + col0 + c] =
            Cs[r * CPITCH + c] + bq[e * F3 + col0 + c];
    }
}

// ---------------- 5) RoPE (in-place) -----------------------------------------
__global__ void k_rope()
{
    int k = blockIdx.x;
    if (k >= g_maxlen) return;
    int eb = blockIdx.y;
    int e = eb / Bdim;
    int tid = threadIdx.x;
    int comp = tid >> 6;
    int i = tid & 63;
    double j2 = (double)(2 * (e * 64 + i));
    double freq = exp(-(j2 / 1024.0) * log(10000.0));
    float angf = (float)k * (float)freq;
    double ss, cc;
    sincos((double)angf, &ss, &cc);
    float c = (float)cc, s = (float)ss;

    float* p = g_qkv + ((size_t)eb * KMAXd + k) * F3 + comp * 256;
    float a = p[128 + 2 * i], bb = p[129 + 2 * i];
    float n0 = p[2 * i], n1 = p[2 * i + 1];
    p[2 * i]       = a * c - bb * s;
    p[2 * i + 1]   = a * s + bb * c;
    p[128 + 2 * i] = n0;
    p[129 + 2 * i] = n1;
}

// ---------------- 6) attention ------------------------------------------------
__global__ void __launch_bounds__(256) k_attn(const float* __restrict__ mask)
{
    int K_len = g_maxlen;
    int q0 = blockIdx.x * 4; if (q0 >= K_len) return;
    int eb = blockIdx.y; int b = eb % Bdim;

    __shared__ float sq[4][256];
    __shared__ float sc[4][KMAXd];
    __shared__ float sred[8];

    int tid = threadIdx.x;
    const float* base = g_qkv + (size_t)eb * KMAXd * F3;
#pragma unroll
    for (int j = 0; j < 4; j++) {
        int q = q0 + j;
        sq[j][tid] = (q < K_len) ? base[(size_t)q * F3 + tid] : 0.f;
    }
    __syncthreads();

    int wid = tid >> 5, lane = tid & 31;
    for (int k = wid; k < K_len; k += 8) {
        const float* kr = base + (size_t)k * F3 + 256;
        float p0 = 0.f, p1 = 0.f, p2 = 0.f, p3 = 0.f;
#pragma unroll
        for (int jj = 0; jj < 8; jj++) {
            int c = lane + jj * 32;
            float kv = kr[c];
            p0 += kv * sq[0][c]; p1 += kv * sq[1][c];
            p2 += kv * sq[2][c]; p3 += kv * sq[3][c];
        }
#pragma unroll
        for (int off = 16; off; off >>= 1) {
            p0 += __shfl_down_sync(0xffffffffu, p0, off);
            p1 += __shfl_down_sync(0xffffffffu, p1, off);
            p2 += __shfl_down_sync(0xffffffffu, p2, off);
            p3 += __shfl_down_sync(0xffffffffu, p3, off);
        }
        if (lane == 0) {
            int sk = g_sid[eb * KMAXd + k];
            float mt = -1000000.0f * (1.0f - mask[b * Sdim + sk]);
            sc[0][k] = p0 * 0.0625f + mt;
            sc[1][k] = p1 * 0.0625f + mt;
            sc[2][k] = p2 * 0.0625f + mt;
            sc[3][k] = p3 * 0.0625f + mt;
        }
    }
    __syncthreads();

    float sinv[4];
    for (int j = 0; j < 4; j++) {
        float lm = -3.0e38f;
        for (int k = tid; k < K_len; k += 256) lm = fmaxf(lm, sc[j][k]);
#pragma unroll
        for (int off = 16; off; off >>= 1)
            lm = fmaxf(lm, __shfl_xor_sync(0xffffffffu, lm, off));
        if (lane == 0) sred[wid] = lm;
        __syncthreads();
        float m8 = sred[0];
#pragma unroll
        for (int w = 1; w < 8; w++) m8 = fmaxf(m8, sred[w]);
        __syncthreads();
        float ls = 0.f;
        for (int k = tid; k < K_len; k += 256) {
            float ev = expf(sc[j][k] - m8);
            sc[j][k] = ev;
            ls += ev;
        }
#pragma unroll
        for (int off = 16; off; off >>= 1)
            ls += __shfl_xor_sync(0xffffffffu, ls, off);
        if (lane == 0) sred[wid] = ls;
        __syncthreads();
        float s8 = 0.f;
#pragma unroll
        for (int w = 0; w < 8; w++) s8 += sred[w];
        sinv[j] = 1.0f / s8;
        __syncthreads();
    }

    float a0 = 0.f, a1 = 0.f, a2 = 0.f, a3 = 0.f;
    const float* vb = base + 512 + tid;
#pragma unroll 8
    for (int k = 0; k < K_len; k++) {
        float vv = vb[(size_t)k * F3];
        a0 += sc[0][k] * vv; a1 += sc[1][k] * vv;
        a2 += sc[2][k] * vv; a3 += sc[3][k] * vv;
    }
    size_t cb = ((size_t)eb * KMAXd + q0) * HDdim + tid;
    float r[4] = {a0 * sinv[0], a1 * sinv[1], a2 * sinv[2], a3 * sinv[3]};
#pragma unroll
    for (int j = 0; j < 4; j++) {
        if (q0 + j < K_len) {
            bf16 h = __float2bfloat16(r[j]);
            g_ctxh[cb + (size_t)j * HDdim] = h;
            g_ctxl[cb + (size_t)j * HDdim] = __float2bfloat16(r[j] - __bfloat162float(h));
        }
    }
}

// ---------------- 7) FF GEMM via split-bf16 HMMA + scatter-add ---------------
__global__ void __launch_bounds__(256) k_ff_mma(const float* __restrict__ bff,
                                                float* __restrict__ out)
{
    int K_len = g_maxlen;
    int row0 = blockIdx.y * 64; if (row0 >= K_len) return;
    int eb = blockIdx.z; int e = eb / Bdim, b = eb % Bdim;
    int col0 = blockIdx.x * 128;

    __shared__ __align__(16) unsigned char sraw[SRAW_BYTES];
    __shared__ int sids[64];
    bf16* Ah = (bf16*)sraw;
    bf16* Al = (bf16*)(sraw + 5120);
    bf16* Bh = (bf16*)(sraw + 10240);
    bf16* Bl = (bf16*)(sraw + 18944);
    float* Cs = (float*)sraw;

    int tid = threadIdx.x;
    if (tid < 64) sids[tid] = g_sid[eb * KMAXd + min(row0 + tid, K_len - 1)];
    __syncthreads();

    int wid = tid >> 5;
    int wr = wid >> 2, wc = wid & 3;

    wmma::fragment<wmma::accumulator, 16, 16, 16, float> acc[2][2];
#pragma unroll
    for (int i = 0; i < 2; i++)
#pragma unroll
        for (int j = 0; j < 2; j++) wmma::fill_fragment(acc[i][j], 0.f);

    const size_t abase = (size_t)eb * KMAXd * HDdim;
    const size_t wbase = (size_t)e * HDdim * Ddim;

    for (int k0 = 0; k0 < HDdim; k0 += 32) {
        {
            int row = tid >> 2, c8 = (tid & 3) * 8;
            size_t src = abase + (size_t)(row0 + row) * HDdim + k0 + c8;
            *(uint4*)&Ah[row * APITCH + c8] = *(const uint4*)&g_ctxh[src];
            *(uint4*)&Al[row * APITCH + c8] = *(const uint4*)&g_ctxl[src];
        }
#pragma unroll
        for (int it = 0; it < 2; it++) {
            int idx = tid + it * 256;
            int row = idx >> 4, c8 = (idx & 15) * 8;
            size_t src = wbase + (size_t)(k0 + row) * Ddim + col0 + c8;
            *(uint4*)&Bh[row * BPITCH + c8] = *(const uint4*)&g_Wfh[src];
            *(uint4*)&Bl[row * BPITCH + c8] = *(const uint4*)&g_Wfl[src];
        }
        __syncthreads();
#pragma unroll
        for (int kk = 0; kk < 32; kk += 16) {
            wmma::fragment<wmma::matrix_a, 16, 16, 16, bf16, wmma::row_major> ah[2], al[2];
            wmma::fragment<wmma::matrix_b, 16, 16, 16, bf16, wmma::row_major> bh[2], bl[2];
#pragma unroll
            for (int i = 0; i < 2; i++) {
                wmma::load_matrix_sync(ah[i], &Ah[(wr * 32 + i * 16) * APITCH + kk], APITCH);
                wmma::load_matrix_sync(al[i], &Al[(wr * 32 + i * 16) * APITCH + kk], APITCH);
            }
#pragma unroll
            for (int j = 0; j < 2; j++) {
                wmma::load_matrix_sync(bh[j], &Bh[kk * BPITCH + wc * 32 + j * 16], BPITCH);
                wmma::load_matrix_sync(bl[j], &Bl[kk * BPITCH + wc * 32 + j * 16], BPITCH);
            }
#pragma unroll
            for (int i = 0; i < 2; i++)
#pragma unroll
                for (int j = 0; j < 2; j++) {
                    wmma::mma_sync(acc[i][j], ah[i], bh[j], acc[i][j]);
                    wmma::mma_sync(acc[i][j], ah[i], bl[j], acc[i][j]);
                    wmma::mma_sync(acc[i][j], al[i], bh[j], acc[i][j]);
                }
        }
        __syncthreads();
    }
#pragma unroll
    for (int i = 0; i < 2; i++)
#pragma unroll
        for (int j = 0; j < 2; j++)
            wmma::store_matrix_sync(&Cs[(wr * 32 + i * 16) * CPITCH + wc * 32 + j * 16],
                                    acc[i][j], CPITCH, wmma::mem_row_major);
    __syncthreads();
    for (int idx = tid; idx < 64 * 128; idx += 256) {
        int r = idx >> 7, c = idx & 127;
        if (row0 + r < K_len) {
            atomicAdd(&out[((size_t)b * Sdim + sids[r]) * Ddim + col0 + c],
                      Cs[r * CPITCH + c] + bff[col0 + c]);
        }
    }
}

// ---------------- launch -----------------------------------------------------
extern "C" void kernel_launch(void* const* d_in, const int* in_sizes, int n_in,
                              void* d_out, int out_size)
{
    const float* X    = (const float*)d_in[0];
    const float* mask = (const float*)d_in[1];
    const float* wg   = (const float*)d_in[2];
    const float* bg   = (const float*)d_in[3];
    const float* Wqkv = (const float*)d_in[4];
    const float* bqkv = (const float*)d_in[5];
    const float* Wff  = (const float*)d_in[6];
    const float* bff  = (const float*)d_in[7];
    float* out = (float*)d_out;

    cudaMemsetAsync(out, 0, (size_t)out_size * sizeof(float));

    // resolve device-global scratch addresses (host side; no allocation)
    bf16 *xh, *xl, *wqh, *wql, *wfh, *wfl;
    cudaGetSymbolAddress((void**)&xh, g_Xh);   cudaGetSymbolAddress((void**)&xl, g_Xl);
    cudaGetSymbolAddress((void**)&wqh, g_Wqh); cudaGetSymbolAddress((void**)&wql, g_Wql);
    cudaGetSymbolAddress((void**)&wfh, g_Wfh); cudaGetSymbolAddress((void**)&wfl, g_Wfl);

    size_t nx  = (size_t)Bdim * Sdim * Ddim / 4;
    size_t nwq = (size_t)Edim * Ddim * F3 / 4;
    size_t nwf = (size_t)Edim * HDdim * Ddim / 4;
    k_cvt<<<(unsigned)((nx  + 255) / 256), 256>>>(X,    xh,  xl,  nx);
    k_cvt<<<(unsigned)((nwq + 255) / 256), 256>>>(Wqkv, wqh, wql, nwq);
    k_cvt<<<(unsigned)((nwf + 255) / 256), 256>>>(Wff,  wfh, wfl, nwf);

    k_gate<<<Bdim * Sdim, 128>>>(X, wg, bg);
    k_reset<<<1, 1>>>();
    k_count<<<EB, 256>>>();
    k_build<<<EB, 256>>>();
    k_qkv_mma<<<dim3(F3 / 128, Sdim / 64, EB), 256>>>(bqkv);
    k_rope<<<dim3(Sdim, EB), 128>>>();
    k_attn<<<dim3(Sdim / 4, EB), 256>>>(mask);
    k_ff_mma<<<dim3(Ddim / 128, Sdim / 64, EB), 256>>>(bff, out);
}

// round 4
// speedup vs baseline: 1.9790x; 1.3731x over previous
#include <cuda_runtime.h>
#include <cuda_bf16.h>
#include <mma.h>
#include <math.h>
#include <stdint.h>

using namespace nvcuda;

#define Bdim  4
#define Sdim  2048
#define Ddim  2048
#define Edim  8
#define HDdim 256
#define F3    768
#define KMAXd 2048
#define EB    (Edim*Bdim)

typedef __nv_bfloat16 bf16;

// ---------------- scratch (device globals; no allocations allowed) ----------
__device__ float g_qkv[(size_t)EB * KMAXd * F3];   // per (e,b,k): [qf|kf|v] after rope
__device__ bf16  g_ctxh[(size_t)EB * KMAXd * HDdim];
__device__ bf16  g_ctxl[(size_t)EB * KMAXd * HDdim];
__device__ bf16  g_Xh[(size_t)Bdim * Sdim * Ddim];
__device__ bf16  g_Xl[(size_t)Bdim * Sdim * Ddim];
__device__ bf16  g_Wqh[(size_t)Edim * Ddim * F3];
__device__ bf16  g_Wql[(size_t)Edim * Ddim * F3];
__device__ bf16  g_Wfh[(size_t)Edim * HDdim * Ddim];
__device__ bf16  g_Wfl[(size_t)Edim * HDdim * Ddim];
__device__ int   g_sid[EB * KMAXd];
__device__ int   g_cnt[EB];
__device__ int   g_maxlen;
__device__ unsigned char g_emask[Bdim * Sdim];

// ---------------- cp.async helpers ------------------------------------------
__device__ __forceinline__ void cpa16(void* smem, const void* gmem)
{
    uint32_t s = (uint32_t)__cvta_generic_to_shared(smem);
    asm volatile("cp.async.cg.shared.global [%0], [%1], 16;\n" :: "r"(s), "l"(gmem));
}
#define CP_COMMIT() asm volatile("cp.async.commit_group;\n" ::: "memory")
#define CP_WAIT(n)  asm volatile("cp.async.wait_group %0;\n" :: "n"(n) : "memory")

// ---------------- 0) fp32 -> bf16 hi/lo split --------------------------------
__global__ void k_cvt(const float* __restrict__ src, bf16* __restrict__ h,
                      bf16* __restrict__ l, size_t n4)
{
    size_t i = (size_t)blockIdx.x * blockDim.x + threadIdx.x;
    if (i >= n4) return;
    float4 v = reinterpret_cast<const float4*>(src)[i];
    bf16 h0 = __float2bfloat16(v.x), h1 = __float2bfloat16(v.y);
    bf16 h2 = __float2bfloat16(v.z), h3 = __float2bfloat16(v.w);
    bf16 l0 = __float2bfloat16(v.x - __bfloat162float(h0));
    bf16 l1 = __float2bfloat16(v.y - __bfloat162float(h1));
    bf16 l2 = __float2bfloat16(v.z - __bfloat162float(h2));
    bf16 l3 = __float2bfloat16(v.w - __bfloat162float(h3));
    reinterpret_cast<ushort4*>(h)[i] = make_ushort4(__bfloat16_as_ushort(h0),
        __bfloat16_as_ushort(h1), __bfloat16_as_ushort(h2), __bfloat16_as_ushort(h3));
    reinterpret_cast<ushort4*>(l)[i] = make_ushort4(__bfloat16_as_ushort(l0),
        __bfloat16_as_ushort(l1), __bfloat16_as_ushort(l2), __bfloat16_as_ushort(l3));
}

// ---------------- 1) gate logits (fp32) + top-2 expert mask -----------------
__global__ void k_gate(const float* __restrict__ X,
                       const float* __restrict__ wg,
                       const float* __restrict__ bg)
{
    int bs = blockIdx.x;
    const float* xr = X + (size_t)bs * Ddim;
    float acc[8];
#pragma unroll
    for (int e = 0; e < 8; e++) acc[e] = 0.f;
    for (int d = threadIdx.x; d < Ddim; d += 128) {
        float xv = xr[d];
        const float4* w = (const float4*)(wg + d * Edim);
        float4 w0 = w[0], w1 = w[1];
        acc[0] = fmaf(xv, w0.x, acc[0]); acc[1] = fmaf(xv, w0.y, acc[1]);
        acc[2] = fmaf(xv, w0.z, acc[2]); acc[3] = fmaf(xv, w0.w, acc[3]);
        acc[4] = fmaf(xv, w1.x, acc[4]); acc[5] = fmaf(xv, w1.y, acc[5]);
        acc[6] = fmaf(xv, w1.z, acc[6]); acc[7] = fmaf(xv, w1.w, acc[7]);
    }
#pragma unroll
    for (int e = 0; e < 8; e++)
#pragma unroll
        for (int off = 16; off; off >>= 1)
            acc[e] += __shfl_down_sync(0xffffffffu, acc[e], off);

    __shared__ float red[4][8];
    int wid = threadIdx.x >> 5, lane = threadIdx.x & 31;
    if (lane == 0) {
#pragma unroll
        for (int e = 0; e < 8; e++) red[wid][e] = acc[e];
    }
    __syncthreads();
    if (threadIdx.x == 0) {
        float v[8];
#pragma unroll
        for (int e = 0; e < 8; e++)
            v[e] = red[0][e] + red[1][e] + red[2][e] + red[3][e] + bg[e];
        int e1 = 0; float b1 = v[0];
#pragma unroll
        for (int e = 1; e < 8; e++) if (v[e] > b1) { b1 = v[e]; e1 = e; }
        int e2 = -1; float b2 = -3.0e38f;
#pragma unroll
        for (int e = 0; e < 8; e++) if (e != e1 && v[e] > b2) { b2 = v[e]; e2 = e; }
        g_emask[bs] = (unsigned char)((1u << e1) | (1u << e2));
    }
}

__global__ void k_reset() { g_maxlen = 0; }

// ---------------- 2) per-(e,b) member counts + global max -------------------
__global__ void k_count()
{
    int eb = blockIdx.x; int e = eb / Bdim, b = eb % Bdim;
    int n = 0;
    for (int s = threadIdx.x; s < Sdim; s += 256)
        n += (g_emask[b * Sdim + s] >> e) & 1;
#pragma unroll
    for (int off = 16; off; off >>= 1) n += __shfl_down_sync(0xffffffffu, n, off);
    __shared__ int sm[8];
    int wid = threadIdx.x >> 5, lane = threadIdx.x & 31;
    if (lane == 0) sm[wid] = n;
    __syncthreads();
    if (threadIdx.x == 0) {
        int t = 0;
#pragma unroll
        for (int w = 0; w < 8; w++) t += sm[w];
        g_cnt[eb] = t;
        atomicMax(&g_maxlen, t);
    }
}

// ---------------- 3) build seq_ids: members + lowest-index zero padding -----
__global__ void k_build()
{
    int eb = blockIdx.x; int e = eb / Bdim, b = eb % Bdim;
    int pad = g_maxlen - g_cnt[eb];
    __shared__ int wsum[8];
    __shared__ int carry;
    if (threadIdx.x == 0) carry = 0;
    __syncthreads();
    int wid = threadIdx.x >> 5, lane = threadIdx.x & 31;
    for (int s0 = 0; s0 < Sdim; s0 += 256) {
        int s = s0 + threadIdx.x;
        int m = (g_emask[b * Sdim + s] >> e) & 1;
        unsigned bal = __ballot_sync(0xffffffffu, m);
        int mp_w = __popc(bal & ((1u << lane) - 1u));
        if (lane == 0) wsum[wid] = __popc(bal);
        __syncthreads();
        int pre = 0;
#pragma unroll
        for (int w = 0; w < 8; w++) if (w < wid) pre += wsum[w];
        int mp  = carry + pre + mp_w;
        int nmb = s - mp;
        bool sel = m || (nmb < pad);
        int pos  = mp + min(nmb, pad);
        if (sel) g_sid[eb * KMAXd + pos] = s;
        __syncthreads();
        if (threadIdx.x == 0) {
            int t = 0;
#pragma unroll
            for (int w = 0; w < 8; w++) t += wsum[w];
            carry += t;
        }
        __syncthreads();
    }
}

// ---------------- GEMM tile geometry -----------------------------------------
// C[64 x 128] per block, split-bf16 (3 mma), KT=32, 2-stage cp.async pipeline.
// per-stage smem: Ah 5120 | Al 5120 | Bh 8704 | Bl 8704  = 27648 B
#define APITCH 40
#define BPITCH 136
#define CPITCH 132
#define STAGE_BYTES 27648
#define SMEM_TOTAL_BYTES (2 * STAGE_BYTES)

struct TilePtrs { bf16 *Ah, *Al, *Bh, *Bl; };
__device__ __forceinline__ TilePtrs stage_ptrs(unsigned char* base, int s)
{
    unsigned char* p = base + s * STAGE_BYTES;
    TilePtrs t;
    t.Ah = (bf16*)p;
    t.Al = (bf16*)(p + 5120);
    t.Bh = (bf16*)(p + 10240);
    t.Bl = (bf16*)(p + 18944);
    return t;
}

// issue one k-tile of loads (A gathered rows, B dense) via cp.async
__device__ __forceinline__ void issue_tile(
    TilePtrs t, int tid,
    const bf16* __restrict__ Ahg, const bf16* __restrict__ Alg, size_t abase,
    const int* sids, int astride, int k0,
    const bf16* __restrict__ Bhg, const bf16* __restrict__ Blg, size_t wbase,
    int bstride, int col0)
{
    {
        int row = tid >> 2, c8 = (tid & 3) * 8;
        size_t src = abase + (size_t)sids[row] * astride + k0 + c8;
        cpa16(&t.Ah[row * APITCH + c8], &Ahg[src]);
        cpa16(&t.Al[row * APITCH + c8], &Alg[src]);
    }
#pragma unroll
    for (int it = 0; it < 2; it++) {
        int idx = tid + it * 256;
        int row = idx >> 4, c8 = (idx & 15) * 8;
        size_t src = wbase + (size_t)(k0 + row) * bstride + col0 + c8;
        cpa16(&t.Bh[row * BPITCH + c8], &Bhg[src]);
        cpa16(&t.Bl[row * BPITCH + c8], &Blg[src]);
    }
}

__device__ __forceinline__ void compute_tile(
    TilePtrs t, int wr, int wc,
    wmma::fragment<wmma::accumulator, 16, 16, 16, float> (&acc)[2][2])
{
#pragma unroll
    for (int kk = 0; kk < 32; kk += 16) {
        wmma::fragment<wmma::matrix_a, 16, 16, 16, bf16, wmma::row_major> ah[2], al[2];
        wmma::fragment<wmma::matrix_b, 16, 16, 16, bf16, wmma::row_major> bh[2], bl[2];
#pragma unroll
        for (int i = 0; i < 2; i++) {
            wmma::load_matrix_sync(ah[i], &t.Ah[(wr * 32 + i * 16) * APITCH + kk], APITCH);
            wmma::load_matrix_sync(al[i], &t.Al[(wr * 32 + i * 16) * APITCH + kk], APITCH);
        }
#pragma unroll
        for (int j = 0; j < 2; j++) {
            wmma::load_matrix_sync(bh[j], &t.Bh[kk * BPITCH + wc * 32 + j * 16], BPITCH);
            wmma::load_matrix_sync(bl[j], &t.Bl[kk * BPITCH + wc * 32 + j * 16], BPITCH);
        }
#pragma unroll
        for (int i = 0; i < 2; i++)
#pragma unroll
            for (int j = 0; j < 2; j++) {
                wmma::mma_sync(acc[i][j], ah[i], bh[j], acc[i][j]);
                wmma::mma_sync(acc[i][j], ah[i], bl[j], acc[i][j]);
                wmma::mma_sync(acc[i][j], al[i], bh[j], acc[i][j]);
            }
    }
}

// ---------------- 4) QKV GEMM -------------------------------------------------
__global__ void __launch_bounds__(256) k_qkv_mma(const float* __restrict__ bq)
{
    int K_len = g_maxlen;
    int row0 = blockIdx.y * 64; if (row0 >= K_len) return;
    int eb = blockIdx.z; int e = eb / Bdim, b = eb % Bdim;
    int col0 = blockIdx.x * 128;

    __shared__ __align__(16) unsigned char sraw[SMEM_TOTAL_BYTES];
    __shared__ int sids[64];
    float* Cs = (float*)sraw;   // epilogue alias (33792 B <= 55296 B)

    int tid = threadIdx.x;
    if (tid < 64) sids[tid] = g_sid[eb * KMAXd + min(row0 + tid, K_len - 1)];
    __syncthreads();

    int wid = tid >> 5;
    int wr = wid >> 2, wc = wid & 3;

    wmma::fragment<wmma::accumulator, 16, 16, 16, float> acc[2][2];
#pragma unroll
    for (int i = 0; i < 2; i++)
#pragma unroll
        for (int j = 0; j < 2; j++) wmma::fill_fragment(acc[i][j], 0.f);

    const size_t xbase = (size_t)b * Sdim * Ddim;
    const size_t wbase = (size_t)e * Ddim * F3;
    const int T = Ddim / 32;

    issue_tile(stage_ptrs(sraw, 0), tid, g_Xh, g_Xl, xbase, sids, Ddim, 0,
               g_Wqh, g_Wql, wbase, F3, col0);
    CP_COMMIT();

    for (int t = 0; t < T; t++) {
        if (t + 1 < T) {
            issue_tile(stage_ptrs(sraw, (t + 1) & 1), tid, g_Xh, g_Xl, xbase,
                       sids, Ddim, (t + 1) * 32, g_Wqh, g_Wql, wbase, F3, col0);
            CP_COMMIT();
            CP_WAIT(1);
        } else {
            CP_WAIT(0);
        }
        __syncthreads();
        compute_tile(stage_ptrs(sraw, t & 1), wr, wc, acc);
        __syncthreads();
    }

#pragma unroll
    for (int i = 0; i < 2; i++)
#pragma unroll
        for (int j = 0; j < 2; j++)
            wmma::store_matrix_sync(&Cs[(wr * 32 + i * 16) * CPITCH + wc * 32 + j * 16],
                                    acc[i][j], CPITCH, wmma::mem_row_major);
    __syncthreads();
    for (int idx = tid; idx < 64 * 128; idx += 256) {
        int r = idx >> 7, c = idx & 127;
        g_qkv[((size_t)eb * KMAXd + row0 + r) * F3 + col0 + c] =
            Cs[r * CPITCH + c] + bq[e * F3 + col0 + c];
    }
}

// ---------------- 5) RoPE (in-place) -----------------------------------------
__global__ void k_rope()
{
    int k = blockIdx.x;
    if (k >= g_maxlen) return;
    int eb = blockIdx.y;
    int e = eb / Bdim;
    int tid = threadIdx.x;
    int comp = tid >> 6;
    int i = tid & 63;
    double j2 = (double)(2 * (e * 64 + i));
    double freq = exp(-(j2 / 1024.0) * log(10000.0));
    float angf = (float)k * (float)freq;
    double ss, cc;
    sincos((double)angf, &ss, &cc);
    float c = (float)cc, s = (float)ss;

    float* p = g_qkv + ((size_t)eb * KMAXd + k) * F3 + comp * 256;
    float a = p[128 + 2 * i], bb = p[129 + 2 * i];
    float n0 = p[2 * i], n1 = p[2 * i + 1];
    p[2 * i]       = a * c - bb * s;
    p[2 * i + 1]   = a * s + bb * c;
    p[128 + 2 * i] = n0;
    p[129 + 2 * i] = n1;
}

// ---------------- 6) attention ------------------------------------------------
__global__ void __launch_bounds__(256) k_attn(const float* __restrict__ mask)
{
    int K_len = g_maxlen;
    int q0 = blockIdx.x * 4; if (q0 >= K_len) return;
    int eb = blockIdx.y; int b = eb % Bdim;

    __shared__ float sq[4][256];
    __shared__ float sc[4][KMAXd];
    __shared__ float sred[8];

    int tid = threadIdx.x;
    const float* base = g_qkv + (size_t)eb * KMAXd * F3;
#pragma unroll
    for (int j = 0; j < 4; j++) {
        int q = q0 + j;
        sq[j][tid] = (q < K_len) ? base[(size_t)q * F3 + tid] : 0.f;
    }
    __syncthreads();

    int wid = tid >> 5, lane = tid & 31;
    for (int k = wid; k < K_len; k += 8) {
        const float* kr = base + (size_t)k * F3 + 256;
        float p0 = 0.f, p1 = 0.f, p2 = 0.f, p3 = 0.f;
#pragma unroll
        for (int jj = 0; jj < 8; jj++) {
            int c = lane + jj * 32;
            float kv = kr[c];
            p0 += kv * sq[0][c]; p1 += kv * sq[1][c];
            p2 += kv * sq[2][c]; p3 += kv * sq[3][c];
        }
#pragma unroll
        for (int off = 16; off; off >>= 1) {
            p0 += __shfl_down_sync(0xffffffffu, p0, off);
            p1 += __shfl_down_sync(0xffffffffu, p1, off);
            p2 += __shfl_down_sync(0xffffffffu, p2, off);
            p3 += __shfl_down_sync(0xffffffffu, p3, off);
        }
        if (lane == 0) {
            int sk = g_sid[eb * KMAXd + k];
            float mt = -1000000.0f * (1.0f - mask[b * Sdim + sk]);
            sc[0][k] = p0 * 0.0625f + mt;
            sc[1][k] = p1 * 0.0625f + mt;
            sc[2][k] = p2 * 0.0625f + mt;
            sc[3][k] = p3 * 0.0625f + mt;
        }
    }
    __syncthreads();

    float sinv[4];
    for (int j = 0; j < 4; j++) {
        float lm = -3.0e38f;
        for (int k = tid; k < K_len; k += 256) lm = fmaxf(lm, sc[j][k]);
#pragma unroll
        for (int off = 16; off; off >>= 1)
            lm = fmaxf(lm, __shfl_xor_sync(0xffffffffu, lm, off));
        if (lane == 0) sred[wid] = lm;
        __syncthreads();
        float m8 = sred[0];
#pragma unroll
        for (int w = 1; w < 8; w++) m8 = fmaxf(m8, sred[w]);
        __syncthreads();
        float ls = 0.f;
        for (int k = tid; k < K_len; k += 256) {
            float ev = expf(sc[j][k] - m8);
            sc[j][k] = ev;
            ls += ev;
        }
#pragma unroll
        for (int off = 16; off; off >>= 1)
            ls += __shfl_xor_sync(0xffffffffu, ls, off);
        if (lane == 0) sred[wid] = ls;
        __syncthreads();
        float s8 = 0.f;
#pragma unroll
        for (int w = 0; w < 8; w++) s8 += sred[w];
        sinv[j] = 1.0f / s8;
        __syncthreads();
    }

    float a0 = 0.f, a1 = 0.f, a2 = 0.f, a3 = 0.f;
    const float* vb = base + 512 + tid;
#pragma unroll 8
    for (int k = 0; k < K_len; k++) {
        float vv = vb[(size_t)k * F3];
        a0 += sc[0][k] * vv; a1 += sc[1][k] * vv;
        a2 += sc[2][k] * vv; a3 += sc[3][k] * vv;
    }
    size_t cb = ((size_t)eb * KMAXd + q0) * HDdim + tid;
    float r[4] = {a0 * sinv[0], a1 * sinv[1], a2 * sinv[2], a3 * sinv[3]};
#pragma unroll
    for (int j = 0; j < 4; j++) {
        if (q0 + j < K_len) {
            bf16 h = __float2bfloat16(r[j]);
            g_ctxh[cb + (size_t)j * HDdim] = h;
            g_ctxl[cb + (size_t)j * HDdim] = __float2bfloat16(r[j] - __bfloat162float(h));
        }
    }
}

// ---------------- 7) FF GEMM + scatter-add ------------------------------------
__global__ void __launch_bounds__(256) k_ff_mma(const float* __restrict__ bff,
                                                float* __restrict__ out)
{
    int K_len = g_maxlen;
    int row0 = blockIdx.y * 64; if (row0 >= K_len) return;
    int eb = blockIdx.z; int e = eb / Bdim, b = eb % Bdim;
    int col0 = blockIdx.x * 128;

    __shared__ __align__(16) unsigned char sraw[SMEM_TOTAL_BYTES];
    __shared__ int sids[64];
    __shared__ int rows[64];
    float* Cs = (float*)sraw;

    int tid = threadIdx.x;
    if (tid < 64) {
        int r = min(row0 + tid, K_len - 1);
        rows[tid] = r;
        sids[tid] = g_sid[eb * KMAXd + r];
    }
    __syncthreads();

    int wid = tid >> 5;
    int wr = wid >> 2, wc = wid & 3;

    wmma::fragment<wmma::accumulator, 16, 16, 16, float> acc[2][2];
#pragma unroll
    for (int i = 0; i < 2; i++)
#pragma unroll
        for (int j = 0; j < 2; j++) wmma::fill_fragment(acc[i][j], 0.f);

    const size_t abase = (size_t)eb * KMAXd * HDdim;
    const size_t wbase = (size_t)e * HDdim * Ddim;
    const int T = HDdim / 32;

    issue_tile(stage_ptrs(sraw, 0), tid, g_ctxh, g_ctxl, abase, rows, HDdim, 0,
               g_Wfh, g_Wfl, wbase, Ddim, col0);
    CP_COMMIT();

    for (int t = 0; t < T; t++) {
        if (t + 1 < T) {
            issue_tile(stage_ptrs(sraw, (t + 1) & 1), tid, g_ctxh, g_ctxl, abase,
                       rows, HDdim, (t + 1) * 32, g_Wfh, g_Wfl, wbase, Ddim, col0);
            CP_COMMIT();
            CP_WAIT(1);
        } else {
            CP_WAIT(0);
        }
        __syncthreads();
        compute_tile(stage_ptrs(sraw, t & 1), wr, wc, acc);
        __syncthreads();
    }

#pragma unroll
    for (int i = 0; i < 2; i++)
#pragma unroll
        for (int j = 0; j < 2; j++)
            wmma::store_matrix_sync(&Cs[(wr * 32 + i * 16) * CPITCH + wc * 32 + j * 16],
                                    acc[i][j], CPITCH, wmma::mem_row_major);
    __syncthreads();
    for (int idx = tid; idx < 64 * 128; idx += 256) {
        int r = idx >> 7, c = idx & 127;
        if (row0 + r < K_len) {
            atomicAdd(&out[((size_t)b * Sdim + sids[r]) * Ddim + col0 + c],
                      Cs[r * CPITCH + c] + bff[col0 + c]);
        }
    }
}

// ---------------- launch -----------------------------------------------------
extern "C" void kernel_launch(void* const* d_in, const int* in_sizes, int n_in,
                              void* d_out, int out_size)
{
    const float* X    = (const float*)d_in[0];
    const float* mask = (const float*)d_in[1];
    const float* wg   = (const float*)d_in[2];
    const float* bg   = (const float*)d_in[3];
    const float* Wqkv = (const float*)d_in[4];
    const float* bqkv = (const float*)d_in[5];
    const float* Wff  = (const float*)d_in[6];
    const float* bff  = (const float*)d_in[7];
    float* out = (float*)d_out;

    cudaMemsetAsync(out, 0, (size_t)out_size * sizeof(float));

    bf16 *xh, *xl, *wqh, *wql, *wfh, *wfl;
    cudaGetSymbolAddress((void**)&xh, g_Xh);   cudaGetSymbolAddress((void**)&xl, g_Xl);
    cudaGetSymbolAddress((void**)&wqh, g_Wqh); cudaGetSymbolAddress((void**)&wql, g_Wql);
    cudaGetSymbolAddress((void**)&wfh, g_Wfh); cudaGetSymbolAddress((void**)&wfl, g_Wfl);

    size_t nx  = (size_t)Bdim * Sdim * Ddim / 4;
    size_t nwq = (size_t)Edim * Ddim * F3 / 4;
    size_t nwf = (size_t)Edim * HDdim * Ddim / 4;
    k_cvt<<<(unsigned)((nx  + 255) / 256), 256>>>(X,    xh,  xl,  nx);
    k_cvt<<<(unsigned)((nwq + 255) / 256), 256>>>(Wqkv, wqh, wql, nwq);
    k_cvt<<<(unsigned)((nwf + 255) / 256), 256>>>(Wff,  wfh, wfl, nwf);

    k_gate<<<Bdim * Sdim, 128>>>(X, wg, bg);
    k_reset<<<1, 1>>>();
    k_count<<<EB, 256>>>();
    k_build<<<EB, 256>>>();
    k_qkv_mma<<<dim3(F3 / 128, Sdim / 64, EB), 256>>>(bqkv);
    k_rope<<<dim3(Sdim, EB), 128>>>();
    k_attn<<<dim3(Sdim / 4, EB), 256>>>(mask);
    k_ff_mma<<<dim3(Ddim / 128, Sdim / 64, EB), 256>>>(bff, out);
}

// round 5
// speedup vs baseline: 2.6330x; 1.3304x over previous
#include <cuda_runtime.h>
#include <cuda_bf16.h>
#include <mma.h>
#include <math.h>
#include <stdint.h>

using namespace nvcuda;

#define Bdim  4
#define Sdim  2048
#define Ddim  2048
#define Edim  8
#define HDdim 256
#define F3    768
#define KMAXd 2048
#define EB    (Edim*Bdim)

typedef __nv_bfloat16 bf16;

// ---------------- scratch (device globals; no allocations allowed) ----------
__device__ float g_qkv[(size_t)EB * KMAXd * F3];   // fp32 QKV GEMM output (pre-rope)
__device__ bf16  g_qkvh[(size_t)EB * KMAXd * F3];  // post-rope split hi
__device__ bf16  g_qkvl[(size_t)EB * KMAXd * F3];  // post-rope split lo
__device__ float g_S[(size_t)EB * KMAXd * KMAXd];  // attention scores scratch
__device__ bf16  g_ctxh[(size_t)EB * KMAXd * HDdim];
__device__ bf16  g_ctxl[(size_t)EB * KMAXd * HDdim];
__device__ bf16  g_Xh[(size_t)Bdim * Sdim * Ddim];
__device__ bf16  g_Xl[(size_t)Bdim * Sdim * Ddim];
__device__ bf16  g_Wqh[(size_t)Edim * Ddim * F3];
__device__ bf16  g_Wql[(size_t)Edim * Ddim * F3];
__device__ bf16  g_Wfh[(size_t)Edim * HDdim * Ddim];
__device__ bf16  g_Wfl[(size_t)Edim * HDdim * Ddim];
__device__ int   g_sid[EB * KMAXd];
__device__ int   g_cnt[EB];
__device__ int   g_maxlen;
__device__ unsigned char g_emask[Bdim * Sdim];

// ---------------- cp.async helpers ------------------------------------------
__device__ __forceinline__ void cpa16(void* smem, const void* gmem)
{
    uint32_t s = (uint32_t)__cvta_generic_to_shared(smem);
    asm volatile("cp.async.cg.shared.global [%0], [%1], 16;\n" :: "r"(s), "l"(gmem));
}
#define CP_COMMIT() asm volatile("cp.async.commit_group;\n" ::: "memory")
#define CP_WAIT(n)  asm volatile("cp.async.wait_group %0;\n" :: "n"(n) : "memory")

// ---------------- 0) fp32 -> bf16 hi/lo split --------------------------------
__global__ void k_cvt(const float* __restrict__ src, bf16* __restrict__ h,
                      bf16* __restrict__ l, size_t n4)
{
    size_t i = (size_t)blockIdx.x * blockDim.x + threadIdx.x;
    if (i >= n4) return;
    float4 v = reinterpret_cast<const float4*>(src)[i];
    bf16 h0 = __float2bfloat16(v.x), h1 = __float2bfloat16(v.y);
    bf16 h2 = __float2bfloat16(v.z), h3 = __float2bfloat16(v.w);
    bf16 l0 = __float2bfloat16(v.x - __bfloat162float(h0));
    bf16 l1 = __float2bfloat16(v.y - __bfloat162float(h1));
    bf16 l2 = __float2bfloat16(v.z - __bfloat162float(h2));
    bf16 l3 = __float2bfloat16(v.w - __bfloat162float(h3));
    reinterpret_cast<ushort4*>(h)[i] = make_ushort4(__bfloat16_as_ushort(h0),
        __bfloat16_as_ushort(h1), __bfloat16_as_ushort(h2), __bfloat16_as_ushort(h3));
    reinterpret_cast<ushort4*>(l)[i] = make_ushort4(__bfloat16_as_ushort(l0),
        __bfloat16_as_ushort(l1), __bfloat16_as_ushort(l2), __bfloat16_as_ushort(l3));
}

// ---------------- 1) gate logits (fp32) + top-2 expert mask -----------------
__global__ void k_gate(const float* __restrict__ X,
                       const float* __restrict__ wg,
                       const float* __restrict__ bg)
{
    int bs = blockIdx.x;
    const float* xr = X + (size_t)bs * Ddim;
    float acc[8];
#pragma unroll
    for (int e = 0; e < 8; e++) acc[e] = 0.f;
    for (int d = threadIdx.x; d < Ddim; d += 128) {
        float xv = xr[d];
        const float4* w = (const float4*)(wg + d * Edim);
        float4 w0 = w[0], w1 = w[1];
        acc[0] = fmaf(xv, w0.x, acc[0]); acc[1] = fmaf(xv, w0.y, acc[1]);
        acc[2] = fmaf(xv, w0.z, acc[2]); acc[3] = fmaf(xv, w0.w, acc[3]);
        acc[4] = fmaf(xv, w1.x, acc[4]); acc[5] = fmaf(xv, w1.y, acc[5]);
        acc[6] = fmaf(xv, w1.z, acc[6]); acc[7] = fmaf(xv, w1.w, acc[7]);
    }
#pragma unroll
    for (int e = 0; e < 8; e++)
#pragma unroll
        for (int off = 16; off; off >>= 1)
            acc[e] += __shfl_down_sync(0xffffffffu, acc[e], off);

    __shared__ float red[4][8];
    int wid = threadIdx.x >> 5, lane = threadIdx.x & 31;
    if (lane == 0) {
#pragma unroll
        for (int e = 0; e < 8; e++) red[wid][e] = acc[e];
    }
    __syncthreads();
    if (threadIdx.x == 0) {
        float v[8];
#pragma unroll
        for (int e = 0; e < 8; e++)
            v[e] = red[0][e] + red[1][e] + red[2][e] + red[3][e] + bg[e];
        int e1 = 0; float b1 = v[0];
#pragma unroll
        for (int e = 1; e < 8; e++) if (v[e] > b1) { b1 = v[e]; e1 = e; }
        int e2 = -1; float b2 = -3.0e38f;
#pragma unroll
        for (int e = 0; e < 8; e++) if (e != e1 && v[e] > b2) { b2 = v[e]; e2 = e; }
        g_emask[bs] = (unsigned char)((1u << e1) | (1u << e2));
    }
}

__global__ void k_reset() { g_maxlen = 0; }

// ---------------- 2) per-(e,b) member counts + global max -------------------
__global__ void k_count()
{
    int eb = blockIdx.x; int e = eb / Bdim, b = eb % Bdim;
    int n = 0;
    for (int s = threadIdx.x; s < Sdim; s += 256)
        n += (g_emask[b * Sdim + s] >> e) & 1;
#pragma unroll
    for (int off = 16; off; off >>= 1) n += __shfl_down_sync(0xffffffffu, n, off);
    __shared__ int sm[8];
    int wid = threadIdx.x >> 5, lane = threadIdx.x & 31;
    if (lane == 0) sm[wid] = n;
    __syncthreads();
    if (threadIdx.x == 0) {
        int t = 0;
#pragma unroll
        for (int w = 0; w < 8; w++) t += sm[w];
        g_cnt[eb] = t;
        atomicMax(&g_maxlen, t);
    }
}

// ---------------- 3) build seq_ids ------------------------------------------
__global__ void k_build()
{
    int eb = blockIdx.x; int e = eb / Bdim, b = eb % Bdim;
    int pad = g_maxlen - g_cnt[eb];
    __shared__ int wsum[8];
    __shared__ int carry;
    if (threadIdx.x == 0) carry = 0;
    __syncthreads();
    int wid = threadIdx.x >> 5, lane = threadIdx.x & 31;
    for (int s0 = 0; s0 < Sdim; s0 += 256) {
        int s = s0 + threadIdx.x;
        int m = (g_emask[b * Sdim + s] >> e) & 1;
        unsigned bal = __ballot_sync(0xffffffffu, m);
        int mp_w = __popc(bal & ((1u << lane) - 1u));
        if (lane == 0) wsum[wid] = __popc(bal);
        __syncthreads();
        int pre = 0;
#pragma unroll
        for (int w = 0; w < 8; w++) if (w < wid) pre += wsum[w];
        int mp  = carry + pre + mp_w;
        int nmb = s - mp;
        bool sel = m || (nmb < pad);
        int pos  = mp + min(nmb, pad);
        if (sel) g_sid[eb * KMAXd + pos] = s;
        __syncthreads();
        if (threadIdx.x == 0) {
            int t = 0;
#pragma unroll
            for (int w = 0; w < 8; w++) t += wsum[w];
            carry += t;
        }
        __syncthreads();
    }
}

// ---------------- GEMM tile machinery (as R4) --------------------------------
#define APITCH 40
#define BPITCH 136
#define CPITCH 132
#define STAGE_BYTES 27648
#define SMEM_TOTAL_BYTES (2 * STAGE_BYTES)

struct TilePtrs { bf16 *Ah, *Al, *Bh, *Bl; };
__device__ __forceinline__ TilePtrs stage_ptrs(unsigned char* base, int s)
{
    unsigned char* p = base + s * STAGE_BYTES;
    TilePtrs t;
    t.Ah = (bf16*)p;
    t.Al = (bf16*)(p + 5120);
    t.Bh = (bf16*)(p + 10240);
    t.Bl = (bf16*)(p + 18944);
    return t;
}

__device__ __forceinline__ void issue_tile(
    TilePtrs t, int tid,
    const bf16* __restrict__ Ahg, const bf16* __restrict__ Alg, size_t abase,
    const int* sids, int astride, int k0,
    const bf16* __restrict__ Bhg, const bf16* __restrict__ Blg, size_t wbase,
    int bstride, int col0)
{
    {
        int row = tid >> 2, c8 = (tid & 3) * 8;
        size_t src = abase + (size_t)sids[row] * astride + k0 + c8;
        cpa16(&t.Ah[row * APITCH + c8], &Ahg[src]);
        cpa16(&t.Al[row * APITCH + c8], &Alg[src]);
    }
#pragma unroll
    for (int it = 0; it < 2; it++) {
        int idx = tid + it * 256;
        int row = idx >> 4, c8 = (idx & 15) * 8;
        size_t src = wbase + (size_t)(k0 + row) * bstride + col0 + c8;
        cpa16(&t.Bh[row * BPITCH + c8], &Bhg[src]);
        cpa16(&t.Bl[row * BPITCH + c8], &Blg[src]);
    }
}

__device__ __forceinline__ void compute_tile(
    TilePtrs t, int wr, int wc,
    wmma::fragment<wmma::accumulator, 16, 16, 16, float> (&acc)[2][2])
{
#pragma unroll
    for (int kk = 0; kk < 32; kk += 16) {
        wmma::fragment<wmma::matrix_a, 16, 16, 16, bf16, wmma::row_major> ah[2], al[2];
        wmma::fragment<wmma::matrix_b, 16, 16, 16, bf16, wmma::row_major> bh[2], bl[2];
#pragma unroll
        for (int i = 0; i < 2; i++) {
            wmma::load_matrix_sync(ah[i], &t.Ah[(wr * 32 + i * 16) * APITCH + kk], APITCH);
            wmma::load_matrix_sync(al[i], &t.Al[(wr * 32 + i * 16) * APITCH + kk], APITCH);
        }
#pragma unroll
        for (int j = 0; j < 2; j++) {
            wmma::load_matrix_sync(bh[j], &t.Bh[kk * BPITCH + wc * 32 + j * 16], BPITCH);
            wmma::load_matrix_sync(bl[j], &t.Bl[kk * BPITCH + wc * 32 + j * 16], BPITCH);
        }
#pragma unroll
        for (int i = 0; i < 2; i++)
#pragma unroll
            for (int j = 0; j < 2; j++) {
                wmma::mma_sync(acc[i][j], ah[i], bh[j], acc[i][j]);
                wmma::mma_sync(acc[i][j], ah[i], bl[j], acc[i][j]);
                wmma::mma_sync(acc[i][j], al[i], bh[j], acc[i][j]);
            }
    }
}

// ---------------- 4) QKV GEMM -------------------------------------------------
__global__ void __launch_bounds__(256) k_qkv_mma(const float* __restrict__ bq)
{
    int K_len = g_maxlen;
    int row0 = blockIdx.y * 64; if (row0 >= K_len) return;
    int eb = blockIdx.z; int e = eb / Bdim, b = eb % Bdim;
    int col0 = blockIdx.x * 128;

    __shared__ __align__(16) unsigned char sraw[SMEM_TOTAL_BYTES];
    __shared__ int sids[64];
    float* Cs = (float*)sraw;

    int tid = threadIdx.x;
    if (tid < 64) sids[tid] = g_sid[eb * KMAXd + min(row0 + tid, K_len - 1)];
    __syncthreads();

    int wid = tid >> 5;
    int wr = wid >> 2, wc = wid & 3;

    wmma::fragment<wmma::accumulator, 16, 16, 16, float> acc[2][2];
#pragma unroll
    for (int i = 0; i < 2; i++)
#pragma unroll
        for (int j = 0; j < 2; j++) wmma::fill_fragment(acc[i][j], 0.f);

    const size_t xbase = (size_t)b * Sdim * Ddim;
    const size_t wbase = (size_t)e * Ddim * F3;
    const int T = Ddim / 32;

    issue_tile(stage_ptrs(sraw, 0), tid, g_Xh, g_Xl, xbase, sids, Ddim, 0,
               g_Wqh, g_Wql, wbase, F3, col0);
    CP_COMMIT();

    for (int t = 0; t < T; t++) {
        if (t + 1 < T) {
            issue_tile(stage_ptrs(sraw, (t + 1) & 1), tid, g_Xh, g_Xl, xbase,
                       sids, Ddim, (t + 1) * 32, g_Wqh, g_Wql, wbase, F3, col0);
            CP_COMMIT();
            CP_WAIT(1);
        } else {
            CP_WAIT(0);
        }
        __syncthreads();
        compute_tile(stage_ptrs(sraw, t & 1), wr, wc, acc);
        __syncthreads();
    }

#pragma unroll
    for (int i = 0; i < 2; i++)
#pragma unroll
        for (int j = 0; j < 2; j++)
            wmma::store_matrix_sync(&Cs[(wr * 32 + i * 16) * CPITCH + wc * 32 + j * 16],
                                    acc[i][j], CPITCH, wmma::mem_row_major);
    __syncthreads();
    for (int idx = tid; idx < 64 * 128; idx += 256) {
        int r = idx >> 7, c = idx & 127;
        g_qkv[((size_t)eb * KMAXd + row0 + r) * F3 + col0 + c] =
            Cs[r * CPITCH + c] + bq[e * F3 + col0 + c];
    }
}

// ---------------- 5) RoPE + split-bf16 convert -------------------------------
__device__ __forceinline__ void wsplit(bf16* oh, bf16* ol, int idx, float v)
{
    bf16 h = __float2bfloat16(v);
    oh[idx] = h;
    ol[idx] = __float2bfloat16(v - __bfloat162float(h));
}

__global__ void k_ropecvt()
{
    int k = blockIdx.x;
    if (k >= g_maxlen) return;
    int eb = blockIdx.y;
    int e = eb / Bdim;
    int tid = threadIdx.x;
    size_t off = ((size_t)eb * KMAXd + k) * F3;
    const float* p = g_qkv + off;
    bf16* oh = g_qkvh + off;
    bf16* ol = g_qkvl + off;

    if (tid < 128) {
        int comp = tid >> 6, i = tid & 63;
        double j2 = (double)(2 * (e * 64 + i));
        double freq = exp(-(j2 / 1024.0) * log(10000.0));
        float angf = (float)k * (float)freq;
        double ss, cc;
        sincos((double)angf, &ss, &cc);
        float c = (float)cc, s = (float)ss;
        const float* q = p + comp * 256;
        float a = q[128 + 2 * i], bb = q[129 + 2 * i];
        float n0 = q[2 * i], n1 = q[2 * i + 1];
        int base = comp * 256;
        wsplit(oh, ol, base + 2 * i,       a * c - bb * s);
        wsplit(oh, ol, base + 2 * i + 1,   a * s + bb * c);
        wsplit(oh, ol, base + 128 + 2 * i, n0);
        wsplit(oh, ol, base + 129 + 2 * i, n1);
    } else {
        int j = tid - 128;
        wsplit(oh, ol, 512 + 2 * j,     p[512 + 2 * j]);
        wsplit(oh, ol, 512 + 2 * j + 1, p[512 + 2 * j + 1]);
    }
}

// ---------------- 6) attention (tensor-core, 2-pass softmax) -----------------
#define QT 64
#define KT 32
#define QP 264
#define KP 264
#define SP 36
#define PP 40
#define OP 260
#define QH_OFF 0
#define QL_OFF 33792
#define PH_OFF 0
#define PL_OFF 5120
#define KH_OFF 67584
#define KL_OFF 84480
#define S_OFF  101376
#define MT_OFF 110592
#define ATTN_SMEM 110720

__global__ void __launch_bounds__(256) k_attn2(const float* __restrict__ mask)
{
    extern __shared__ unsigned char dsm[];
    int K_len = g_maxlen;
    int q0 = blockIdx.x * QT; if (q0 >= K_len) return;
    int eb = blockIdx.y; int b = eb % Bdim;
    int tid = threadIdx.x, wid = tid >> 5;
    int rg = wid & 3, cg = wid >> 2;

    bf16* Qh = (bf16*)(dsm + QH_OFF);
    bf16* Ql = (bf16*)(dsm + QL_OFF);
    bf16* Kh = (bf16*)(dsm + KH_OFF);
    bf16* Kl = (bf16*)(dsm + KL_OFF);
    float* Ssm = (float*)(dsm + S_OFF);
    bf16* Ph = (bf16*)(dsm + PH_OFF);      // aliases Q region (pass B only)
    bf16* Pl = (bf16*)(dsm + PL_OFF);
    float* mt = (float*)(dsm + MT_OFF);
    float* Ost = (float*)dsm;              // epilogue alias over Q region

    const size_t rowbase = (size_t)eb * KMAXd;

    // load Q tile (64 x 256 hi/lo)
    {
        const bf16* qh = g_qkvh + (rowbase + q0) * F3;
        const bf16* ql = g_qkvl + (rowbase + q0) * F3;
#pragma unroll
        for (int it = 0; it < 8; it++) {
            int idx = tid + it * 256;
            int r = idx >> 5, c8 = (idx & 31) * 8;
            *(uint4*)&Qh[r * QP + c8] = *(const uint4*)&qh[(size_t)r * F3 + c8];
            *(uint4*)&Ql[r * QP + c8] = *(const uint4*)&ql[(size_t)r * F3 + c8];
        }
    }
    __syncthreads();

    int NT = (K_len + KT - 1) / KT;
    int rrow = tid >> 2, cbase = (tid & 3) * 8;
    float m_run = -3.0e38f;
    float* srow = g_S + ((size_t)eb * KMAXd + q0 + rrow) * KMAXd;

    // ---- pass A: S tiles -> gmem, track row max in registers ----
    for (int kt = 0; kt < NT; kt++) {
        {
            const bf16* kh = g_qkvh + (rowbase + (size_t)kt * KT) * F3 + 256;
            const bf16* kl = g_qkvl + (rowbase + (size_t)kt * KT) * F3 + 256;
#pragma unroll
            for (int it = 0; it < 4; it++) {
                int idx = tid + it * 256;
                int r = idx >> 5, c8 = (idx & 31) * 8;
                *(uint4*)&Kh[r * KP + c8] = *(const uint4*)&kh[(size_t)r * F3 + c8];
                *(uint4*)&Kl[r * KP + c8] = *(const uint4*)&kl[(size_t)r * F3 + c8];
            }
        }
        if (tid < KT) {
            int k = kt * KT + tid;
            mt[tid] = (k < K_len)
                ? -1000000.0f * (1.0f - mask[b * Sdim + g_sid[eb * KMAXd + k]])
                : -1.0e30f;
        }
        __syncthreads();
        {
            wmma::fragment<wmma::accumulator, 16, 16, 16, float> sf;
            wmma::fill_fragment(sf, 0.f);
#pragma unroll
            for (int k16 = 0; k16 < 256; k16 += 16) {
                wmma::fragment<wmma::matrix_a, 16, 16, 16, bf16, wmma::row_major> ah, al;
                wmma::fragment<wmma::matrix_b, 16, 16, 16, bf16, wmma::col_major> bh, bl;
                wmma::load_matrix_sync(ah, &Qh[(rg * 16) * QP + k16], QP);
                wmma::load_matrix_sync(al, &Ql[(rg * 16) * QP + k16], QP);
                wmma::load_matrix_sync(bh, &Kh[(cg * 16) * KP + k16], KP);
                wmma::load_matrix_sync(bl, &Kl[(cg * 16) * KP + k16], KP);
                wmma::mma_sync(sf, ah, bh, sf);
                wmma::mma_sync(sf, ah, bl, sf);
                wmma::mma_sync(sf, al, bh, sf);
            }
            wmma::store_matrix_sync(&Ssm[(rg * 16) * SP + cg * 16], sf, SP,
                                    wmma::mem_row_major);
        }
        __syncthreads();
        {
            float sv[8]; float tmax = -3.0e38f;
#pragma unroll
            for (int i = 0; i < 8; i++) {
                sv[i] = Ssm[rrow * SP + cbase + i] * 0.0625f + mt[cbase + i];
                tmax = fmaxf(tmax, sv[i]);
            }
            tmax = fmaxf(tmax, __shfl_xor_sync(0xffffffffu, tmax, 1));
            tmax = fmaxf(tmax, __shfl_xor_sync(0xffffffffu, tmax, 2));
            m_run = fmaxf(m_run, tmax);
            *(float4*)&srow[kt * KT + cbase]     = make_float4(sv[0], sv[1], sv[2], sv[3]);
            *(float4*)&srow[kt * KT + cbase + 4] = make_float4(sv[4], sv[5], sv[6], sv[7]);
        }
        __syncthreads();
    }

    // ---- pass B: p = exp(s - m), accumulate l and O = P@V ----
    float l_run = 0.f;
    wmma::fragment<wmma::accumulator, 16, 16, 16, float> of[8];
#pragma unroll
    for (int j = 0; j < 8; j++) wmma::fill_fragment(of[j], 0.f);

    for (int kt = 0; kt < NT; kt++) {
        {
            float4 v0 = *(const float4*)&srow[kt * KT + cbase];
            float4 v1 = *(const float4*)&srow[kt * KT + cbase + 4];
            float pv[8] = {v0.x, v0.y, v0.z, v0.w, v1.x, v1.y, v1.z, v1.w};
            float ls = 0.f;
#pragma unroll
            for (int i = 0; i < 8; i++) { pv[i] = __expf(pv[i] - m_run); ls += pv[i]; }
            ls += __shfl_xor_sync(0xffffffffu, ls, 1);
            ls += __shfl_xor_sync(0xffffffffu, ls, 2);
            l_run += ls;
#pragma unroll
            for (int i = 0; i < 8; i += 2) {
                __nv_bfloat162 h2 = __float22bfloat162_rn(make_float2(pv[i], pv[i + 1]));
                float2 back = __bfloat1622float2(h2);
                __nv_bfloat162 l2 = __float22bfloat162_rn(
                    make_float2(pv[i] - back.x, pv[i + 1] - back.y));
                *(__nv_bfloat162*)&Ph[rrow * PP + cbase + i] = h2;
                *(__nv_bfloat162*)&Pl[rrow * PP + cbase + i] = l2;
            }
        }
        {
            const bf16* vh = g_qkvh + (rowbase + (size_t)kt * KT) * F3 + 512;
            const bf16* vl = g_qkvl + (rowbase + (size_t)kt * KT) * F3 + 512;
#pragma unroll
            for (int it = 0; it < 4; it++) {
                int idx = tid + it * 256;
                int r = idx >> 5, c8 = (idx & 31) * 8;
                *(uint4*)&Kh[r * KP + c8] = *(const uint4*)&vh[(size_t)r * F3 + c8];
                *(uint4*)&Kl[r * KP + c8] = *(const uint4*)&vl[(size_t)r * F3 + c8];
            }
        }
        __syncthreads();
#pragma unroll
        for (int kk = 0; kk < KT; kk += 16) {
            wmma::fragment<wmma::matrix_a, 16, 16, 16, bf16, wmma::row_major> pah, pal;
            wmma::load_matrix_sync(pah, &Ph[(rg * 16) * PP + kk], PP);
            wmma::load_matrix_sync(pal, &Pl[(rg * 16) * PP + kk], PP);
#pragma unroll
            for (int j = 0; j < 8; j++) {
                wmma::fragment<wmma::matrix_b, 16, 16, 16, bf16, wmma::row_major> vbh, vbl;
                wmma::load_matrix_sync(vbh, &Kh[kk * KP + cg * 128 + j * 16], KP);
                wmma::load_matrix_sync(vbl, &Kl[kk * KP + cg * 128 + j * 16], KP);
                wmma::mma_sync(of[j], pah, vbh, of[j]);
                wmma::mma_sync(of[j], pah, vbl, of[j]);
                wmma::mma_sync(of[j], pal, vbh, of[j]);
            }
        }
        __syncthreads();
    }

    // ---- epilogue: O/l -> ctx hi/lo ----
#pragma unroll
    for (int j = 0; j < 8; j++)
        wmma::store_matrix_sync(&Ost[(rg * 16) * OP + cg * 128 + j * 16], of[j], OP,
                                wmma::mem_row_major);
    __syncthreads();
    if (q0 + rrow < K_len) {
        float inv = 1.0f / l_run;
        size_t obase = (rowbase + q0 + rrow) * HDdim + (size_t)(tid & 3) * 64;
        int sb = rrow * OP + (tid & 3) * 64;
#pragma unroll
        for (int c = 0; c < 64; c += 2) {
            float o0 = Ost[sb + c] * inv, o1 = Ost[sb + c + 1] * inv;
            __nv_bfloat162 h2 = __float22bfloat162_rn(make_float2(o0, o1));
            float2 back = __bfloat1622float2(h2);
            __nv_bfloat162 l2 = __float22bfloat162_rn(make_float2(o0 - back.x, o1 - back.y));
            *(__nv_bfloat162*)&g_ctxh[obase + c] = h2;
            *(__nv_bfloat162*)&g_ctxl[obase + c] = l2;
        }
    }
}

// ---------------- 7) FF GEMM + scatter-add ------------------------------------
__global__ void __launch_bounds__(256) k_ff_mma(const float* __restrict__ bff,
                                                float* __restrict__ out)
{
    int K_len = g_maxlen;
    int row0 = blockIdx.y * 64; if (row0 >= K_len) return;
    int eb = blockIdx.z; int e = eb / Bdim, b = eb % Bdim;
    int col0 = blockIdx.x * 128;

    __shared__ __align__(16) unsigned char sraw[SMEM_TOTAL_BYTES];
    __shared__ int sids[64];
    __shared__ int rows[64];
    float* Cs = (float*)sraw;

    int tid = threadIdx.x;
    if (tid < 64) {
        int r = min(row0 + tid, K_len - 1);
        rows[tid] = r;
        sids[tid] = g_sid[eb * KMAXd + r];
    }
    __syncthreads();

    int wid = tid >> 5;
    int wr = wid >> 2, wc = wid & 3;

    wmma::fragment<wmma::accumulator, 16, 16, 16, float> acc[2][2];
#pragma unroll
    for (int i = 0; i < 2; i++)
#pragma unroll
        for (int j = 0; j < 2; j++) wmma::fill_fragment(acc[i][j], 0.f);

    const size_t abase = (size_t)eb * KMAXd * HDdim;
    const size_t wbase = (size_t)e * HDdim * Ddim;
    const int T = HDdim / 32;

    issue_tile(stage_ptrs(sraw, 0), tid, g_ctxh, g_ctxl, abase, rows, HDdim, 0,
               g_Wfh, g_Wfl, wbase, Ddim, col0);
    CP_COMMIT();

    for (int t = 0; t < T; t++) {
        if (t + 1 < T) {
            issue_tile(stage_ptrs(sraw, (t + 1) & 1), tid, g_ctxh, g_ctxl, abase,
                       rows, HDdim, (t + 1) * 32, g_Wfh, g_Wfl, wbase, Ddim, col0);
            CP_COMMIT();
            CP_WAIT(1);
        } else {
            CP_WAIT(0);
        }
        __syncthreads();
        compute_tile(stage_ptrs(sraw, t & 1), wr, wc, acc);
        __syncthreads();
    }

#pragma unroll
    for (int i = 0; i < 2; i++)
#pragma unroll
        for (int j = 0; j < 2; j++)
            wmma::store_matrix_sync(&Cs[(wr * 32 + i * 16) * CPITCH + wc * 32 + j * 16],
                                    acc[i][j], CPITCH, wmma::mem_row_major);
    __syncthreads();
    for (int idx = tid; idx < 64 * 128; idx += 256) {
        int r = idx >> 7, c = idx & 127;
        if (row0 + r < K_len) {
            atomicAdd(&out[((size_t)b * Sdim + sids[r]) * Ddim + col0 + c],
                      Cs[r * CPITCH + c] + bff[col0 + c]);
        }
    }
}

// ---------------- launch -----------------------------------------------------
extern "C" void kernel_launch(void* const* d_in, const int* in_sizes, int n_in,
                              void* d_out, int out_size)
{
    const float* X    = (const float*)d_in[0];
    const float* mask = (const float*)d_in[1];
    const float* wg   = (const float*)d_in[2];
    const float* bg   = (const float*)d_in[3];
    const float* Wqkv = (const float*)d_in[4];
    const float* bqkv = (const float*)d_in[5];
    const float* Wff  = (const float*)d_in[6];
    const float* bff  = (const float*)d_in[7];
    float* out = (float*)d_out;

    cudaFuncSetAttribute(k_attn2, cudaFuncAttributeMaxDynamicSharedMemorySize,
                         ATTN_SMEM);

    cudaMemsetAsync(out, 0, (size_t)out_size * sizeof(float));

    bf16 *xh, *xl, *wqh, *wql, *wfh, *wfl;
    cudaGetSymbolAddress((void**)&xh, g_Xh);   cudaGetSymbolAddress((void**)&xl, g_Xl);
    cudaGetSymbolAddress((void**)&wqh, g_Wqh); cudaGetSymbolAddress((void**)&wql, g_Wql);
    cudaGetSymbolAddress((void**)&wfh, g_Wfh); cudaGetSymbolAddress((void**)&wfl, g_Wfl);

    size_t nx  = (size_t)Bdim * Sdim * Ddim / 4;
    size_t nwq = (size_t)Edim * Ddim * F3 / 4;
    size_t nwf = (size_t)Edim * HDdim * Ddim / 4;
    k_cvt<<<(unsigned)((nx  + 255) / 256), 256>>>(X,    xh,  xl,  nx);
    k_cvt<<<(unsigned)((nwq + 255) / 256), 256>>>(Wqkv, wqh, wql, nwq);
    k_cvt<<<(unsigned)((nwf + 255) / 256), 256>>>(Wff,  wfh, wfl, nwf);

    k_gate<<<Bdim * Sdim, 128>>>(X, wg, bg);
    k_reset<<<1, 1>>>();
    k_count<<<EB, 256>>>();
    k_build<<<EB, 256>>>();
    k_qkv_mma<<<dim3(F3 / 128, Sdim / 64, EB), 256>>>(bqkv);
    k_ropecvt<<<dim3(Sdim, EB), 256>>>();
    k_attn2<<<dim3(Sdim / QT, EB), 256, ATTN_SMEM>>>(mask);
    k_ff_mma<<<dim3(Ddim / 128, Sdim / 64, EB), 256>>>(bff, out);
}

// round 7
// speedup vs baseline: 4.4814x; 1.7020x over previous
#include <cuda_runtime.h>
#include <cuda_fp16.h>
#include <mma.h>
#include <math.h>
#include <stdint.h>

using namespace nvcuda;

#define Bdim  4
#define Sdim  2048
#define Ddim  2048
#define Edim  8
#define HDdim 256
#define F3    768
#define KMAXd 2048
#define EB    (Edim*Bdim)

typedef __half f16;

// ---------------- scratch (device globals; no allocations allowed) ----------
__device__ f16   g_qkvh[(size_t)EB * KMAXd * F3];  // post-rope [qf|kf|v] hi
__device__ f16   g_qkvl[(size_t)EB * KMAXd * F3];  // lo
__device__ float g_S[(size_t)EB * KMAXd * KMAXd];  // attention scores scratch
__device__ f16   g_ctxh[(size_t)EB * KMAXd * HDdim];
__device__ f16   g_Xh[(size_t)Bdim * Sdim * Ddim];
__device__ f16   g_Wqh[(size_t)Edim * Ddim * F3];
__device__ f16   g_Wql[(size_t)Edim * Ddim * F3];
__device__ f16   g_Wfh[(size_t)Edim * HDdim * Ddim];
__device__ f16   g_Wfl[(size_t)Edim * HDdim * Ddim];
__device__ float g_tcos[KMAXd * 512];
__device__ float g_tsin[KMAXd * 512];
__device__ int   g_sid[EB * KMAXd];
__device__ int   g_cnt[EB];
__device__ int   g_maxlen;
__device__ unsigned char g_emask[Bdim * Sdim];

// ---------------- cp.async helpers ------------------------------------------
__device__ __forceinline__ void cpa16(void* smem, const void* gmem)
{
    uint32_t s = (uint32_t)__cvta_generic_to_shared(smem);
    asm volatile("cp.async.cg.shared.global [%0], [%1], 16;\n" :: "r"(s), "l"(gmem));
}
#define CP_COMMIT() asm volatile("cp.async.commit_group;\n" ::: "memory")
#define CP_WAIT(n)  asm volatile("cp.async.wait_group %0;\n" :: "n"(n) : "memory")

// ---------------- 0a) fp32 -> fp16 single ------------------------------------
__global__ void k_cvtX(const float* __restrict__ src, f16* __restrict__ h, size_t n4)
{
    size_t i = (size_t)blockIdx.x * blockDim.x + threadIdx.x;
    if (i >= n4) return;
    float4 v = reinterpret_cast<const float4*>(src)[i];
    __half2 h01 = __floats2half2_rn(v.x, v.y);
    __half2 h23 = __floats2half2_rn(v.z, v.w);
    reinterpret_cast<uint2*>(h)[i] =
        make_uint2(*(uint32_t*)&h01, *(uint32_t*)&h23);
}

// ---------------- 0b) fp32 -> fp16 hi/lo split --------------------------------
__global__ void k_cvtW(const float* __restrict__ src, f16* __restrict__ h,
                       f16* __restrict__ l, size_t n4)
{
    size_t i = (size_t)blockIdx.x * blockDim.x + threadIdx.x;
    if (i >= n4) return;
    float4 v = reinterpret_cast<const float4*>(src)[i];
    __half2 h01 = __floats2half2_rn(v.x, v.y);
    __half2 h23 = __floats2half2_rn(v.z, v.w);
    float2 b01 = __half22float2(h01), b23 = __half22float2(h23);
    __half2 l01 = __floats2half2_rn(v.x - b01.x, v.y - b01.y);
    __half2 l23 = __floats2half2_rn(v.z - b23.x, v.w - b23.y);
    reinterpret_cast<uint2*>(h)[i] = make_uint2(*(uint32_t*)&h01, *(uint32_t*)&h23);
    reinterpret_cast<uint2*>(l)[i] = make_uint2(*(uint32_t*)&l01, *(uint32_t*)&l23);
}

// ---------------- 0c) rope tables: cos/sin[k][j], j = e*64+i ------------------
__global__ void k_rtab()
{
    int k = blockIdx.x, j = threadIdx.x;
    double freq = exp(((double)(-2 * j) / 1024.0) * log(10000.0));
    double ang = (double)k * freq;
    double ss, cc;
    sincos(ang, &ss, &cc);
    g_tcos[k * 512 + j] = (float)cc;
    g_tsin[k * 512 + j] = (float)ss;
}

// ---------------- 1) gate logits (fp32) + top-2 expert mask -----------------
__global__ void k_gate(const float* __restrict__ X,
                       const float* __restrict__ wg,
                       const float* __restrict__ bg)
{
    int bs = blockIdx.x;
    const float* xr = X + (size_t)bs * Ddim;
    float acc[8];
#pragma unroll
    for (int e = 0; e < 8; e++) acc[e] = 0.f;
    for (int d = threadIdx.x; d < Ddim; d += 128) {
        float xv = xr[d];
        const float4* w = (const float4*)(wg + d * Edim);
        float4 w0 = w[0], w1 = w[1];
        acc[0] = fmaf(xv, w0.x, acc[0]); acc[1] = fmaf(xv, w0.y, acc[1]);
        acc[2] = fmaf(xv, w0.z, acc[2]); acc[3] = fmaf(xv, w0.w, acc[3]);
        acc[4] = fmaf(xv, w1.x, acc[4]); acc[5] = fmaf(xv, w1.y, acc[5]);
        acc[6] = fmaf(xv, w1.z, acc[6]); acc[7] = fmaf(xv, w1.w, acc[7]);
    }
#pragma unroll
    for (int e = 0; e < 8; e++)
#pragma unroll
        for (int off = 16; off; off >>= 1)
            acc[e] += __shfl_down_sync(0xffffffffu, acc[e], off);

    __shared__ float red[4][8];
    int wid = threadIdx.x >> 5, lane = threadIdx.x & 31;
    if (lane == 0) {
#pragma unroll
        for (int e = 0; e < 8; e++) red[wid][e] = acc[e];
    }
    __syncthreads();
    if (threadIdx.x == 0) {
        float v[8];
#pragma unroll
        for (int e = 0; e < 8; e++)
            v[e] = red[0][e] + red[1][e] + red[2][e] + red[3][e] + bg[e];
        int e1 = 0; float b1 = v[0];
#pragma unroll
        for (int e = 1; e < 8; e++) if (v[e] > b1) { b1 = v[e]; e1 = e; }
        int e2 = -1; float b2 = -3.0e38f;
#pragma unroll
        for (int e = 0; e < 8; e++) if (e != e1 && v[e] > b2) { b2 = v[e]; e2 = e; }
        g_emask[bs] = (unsigned char)((1u << e1) | (1u << e2));
    }
}

__global__ void k_reset() { g_maxlen = 0; }

// ---------------- 2) per-(e,b) member counts + global max -------------------
__global__ void k_count()
{
    int eb = blockIdx.x; int e = eb / Bdim, b = eb % Bdim;
    int n = 0;
    for (int s = threadIdx.x; s < Sdim; s += 256)
        n += (g_emask[b * Sdim + s] >> e) & 1;
#pragma unroll
    for (int off = 16; off; off >>= 1) n += __shfl_down_sync(0xffffffffu, n, off);
    __shared__ int sm[8];
    int wid = threadIdx.x >> 5, lane = threadIdx.x & 31;
    if (lane == 0) sm[wid] = n;
    __syncthreads();
    if (threadIdx.x == 0) {
        int t = 0;
#pragma unroll
        for (int w = 0; w < 8; w++) t += sm[w];
        g_cnt[eb] = t;
        atomicMax(&g_maxlen, t);
    }
}

// ---------------- 3) build seq_ids ------------------------------------------
__global__ void k_build()
{
    int eb = blockIdx.x; int e = eb / Bdim, b = eb % Bdim;
    int pad = g_maxlen - g_cnt[eb];
    __shared__ int wsum[8];
    __shared__ int carry;
    if (threadIdx.x == 0) carry = 0;
    __syncthreads();
    int wid = threadIdx.x >> 5, lane = threadIdx.x & 31;
    for (int s0 = 0; s0 < Sdim; s0 += 256) {
        int s = s0 + threadIdx.x;
        int m = (g_emask[b * Sdim + s] >> e) & 1;
        unsigned bal = __ballot_sync(0xffffffffu, m);
        int mp_w = __popc(bal & ((1u << lane) - 1u));
        if (lane == 0) wsum[wid] = __popc(bal);
        __syncthreads();
        int pre = 0;
#pragma unroll
        for (int w = 0; w < 8; w++) if (w < wid) pre += wsum[w];
        int mp  = carry + pre + mp_w;
        int nmb = s - mp;
        bool sel = m || (nmb < pad);
        int pos  = mp + min(nmb, pad);
        if (sel) g_sid[eb * KMAXd + pos] = s;
        __syncthreads();
        if (threadIdx.x == 0) {
            int t = 0;
#pragma unroll
            for (int w = 0; w < 8; w++) t += wsum[w];
            carry += t;
        }
        __syncthreads();
    }
}

// ---------------- GEMM tile machinery (2-term fp16) ---------------------------
// C[64 x 128] per block; A single fp16 (gathered), B hi/lo; KT=32, 2-stage.
// stage: A@0 (5120 B) | Bh@5120 (8704) | Bl@13824 (8704) = 22528 B
#define APITCH 40
#define BPITCH 136
#define CPITCH 132
#define GSTAGE 22528

struct GT { f16 *A, *Bh, *Bl; };
__device__ __forceinline__ GT gstage(unsigned char* base, int s)
{
    unsigned char* p = base + s * GSTAGE;
    GT t; t.A = (f16*)p; t.Bh = (f16*)(p + 5120); t.Bl = (f16*)(p + 13824);
    return t;
}

__device__ __forceinline__ void g_issue(
    GT t, int tid, const f16* __restrict__ Ag, const int* rows, int astr, int k0,
    const f16* __restrict__ Bhg, const f16* __restrict__ Blg, int bstr, int col0)
{
    {
        int row = tid >> 2, c8 = (tid & 3) * 8;
        cpa16(&t.A[row * APITCH + c8], Ag + (size_t)rows[row] * astr + k0 + c8);
    }
#pragma unroll
    for (int it = 0; it < 2; it++) {
        int idx = tid + it * 256;
        int row = idx >> 4, c8 = (idx & 15) * 8;
        size_t src = (size_t)(k0 + row) * bstr + col0 + c8;
        cpa16(&t.Bh[row * BPITCH + c8], Bhg + src);
        cpa16(&t.Bl[row * BPITCH + c8], Blg + src);
    }
}

__device__ __forceinline__ void g_comp(
    GT t, int wr, int wc,
    wmma::fragment<wmma::accumulator, 16, 16, 16, float> (&acc)[2][2])
{
#pragma unroll
    for (int kk = 0; kk < 32; kk += 16) {
        wmma::fragment<wmma::matrix_a, 16, 16, 16, half, wmma::row_major> a[2];
        wmma::fragment<wmma::matrix_b, 16, 16, 16, half, wmma::row_major> bh[2], bl[2];
#pragma unroll
        for (int i = 0; i < 2; i++)
            wmma::load_matrix_sync(a[i], &t.A[(wr * 32 + i * 16) * APITCH + kk], APITCH);
#pragma unroll
        for (int j = 0; j < 2; j++) {
            wmma::load_matrix_sync(bh[j], &t.Bh[kk * BPITCH + wc * 32 + j * 16], BPITCH);
            wmma::load_matrix_sync(bl[j], &t.Bl[kk * BPITCH + wc * 32 + j * 16], BPITCH);
        }
#pragma unroll
        for (int i = 0; i < 2; i++)
#pragma unroll
            for (int j = 0; j < 2; j++) {
                wmma::mma_sync(acc[i][j], a[i], bh[j], acc[i][j]);
                wmma::mma_sync(acc[i][j], a[i], bl[j], acc[i][j]);
            }
    }
}

// ---------------- 4) QKV GEMM + fused rope/split epilogue --------------------
__global__ void __launch_bounds__(256) k_qkv(const float* __restrict__ bq)
{
    int K_len = g_maxlen;
    int row0 = blockIdx.y * 64; if (row0 >= K_len) return;
    int eb = blockIdx.z; int e = eb / Bdim, b = eb % Bdim;
    int col0 = blockIdx.x * 128;

    __shared__ __align__(16) unsigned char sraw[2 * GSTAGE];
    __shared__ int sids[64];
    float* Cs = (float*)sraw;   // epilogue alias: 64*132*4 = 33792 <= 45056

    int tid = threadIdx.x;
    if (tid < 64) sids[tid] = g_sid[eb * KMAXd + min(row0 + tid, K_len - 1)];
    __syncthreads();

    int wid = tid >> 5;
    int wr = wid >> 2, wc = wid & 3;

    wmma::fragment<wmma::accumulator, 16, 16, 16, float> acc[2][2];
#pragma unroll
    for (int i = 0; i < 2; i++)
#pragma unroll
        for (int j = 0; j < 2; j++) wmma::fill_fragment(acc[i][j], 0.f);

    const f16* Ag  = g_Xh + (size_t)b * Sdim * Ddim;
    const f16* Bhg = g_Wqh + (size_t)e * Ddim * F3;
    const f16* Blg = g_Wql + (size_t)e * Ddim * F3;
    const int T = Ddim / 32;

    g_issue(gstage(sraw, 0), tid, Ag, sids, Ddim, 0, Bhg, Blg, F3, col0);
    CP_COMMIT();
    for (int t = 0; t < T; t++) {
        if (t + 1 < T) {
            g_issue(gstage(sraw, (t + 1) & 1), tid, Ag, sids, Ddim, (t + 1) * 32,
                    Bhg, Blg, F3, col0);
            CP_COMMIT();
            CP_WAIT(1);
        } else {
            CP_WAIT(0);
        }
        __syncthreads();
        g_comp(gstage(sraw, t & 1), wr, wc, acc);
        __syncthreads();
    }

#pragma unroll
    for (int i = 0; i < 2; i++)
#pragma unroll
        for (int j = 0; j < 2; j++)
            wmma::store_matrix_sync(&Cs[(wr * 32 + i * 16) * CPITCH + wc * 32 + j * 16],
                                    acc[i][j], CPITCH, wmma::mem_row_major);
    __syncthreads();

    // fused: bias + rope + fp16 hi/lo split, with nope/pe half swap
    int blk = col0 >> 8;               // 0=q, 1=k, 2=v
    int halfsel = (col0 >> 7) & 1;     // 0 = nope half (q/k), 1 = pe half
    int obase = blk * 256;
    const float* bqe = bq + e * F3 + col0;
    for (int idx = tid; idx < 64 * 64; idx += 256) {
        int r = idx >> 6, p = idx & 63;
        int grow = row0 + r;
        if (grow >= K_len) continue;
        float v0 = Cs[r * CPITCH + 2 * p]     + bqe[2 * p];
        float v1 = Cs[r * CPITCH + 2 * p + 1] + bqe[2 * p + 1];
        int outc;
        if (blk == 2) {
            outc = col0 + 2 * p;
        } else if (halfsel == 0) {
            outc = obase + 128 + 2 * p;
        } else {
            int ti = grow * 512 + e * 64 + p;
            float c = g_tcos[ti], s = g_tsin[ti];
            float r0 = v0 * c - v1 * s;
            float r1 = v0 * s + v1 * c;
            v0 = r0; v1 = r1;
            outc = obase + 2 * p;
        }
        size_t off = ((size_t)eb * KMAXd + grow) * F3 + outc;
        __half2 h2 = __floats2half2_rn(v0, v1);
        float2 back = __half22float2(h2);
        __half2 l2 = __floats2half2_rn(v0 - back.x, v1 - back.y);
        *(__half2*)&g_qkvh[off] = h2;
        *(__half2*)&g_qkvl[off] = l2;
    }
}

// ---------------- 5) attention (fp16 tensor-core, 2-pass softmax) -------------
#define QT 64
#define KT 32
#define QP 264
#define KP 264
#define SP 36
#define PP 40
#define OP 260
#define AQ   0
#define AKH  33792
#define AKL  50688
#define AS   67584
#define AMT  76800
#define APH  0
#define AO   5120
#define ATTN_SMEM 76928

__global__ void __launch_bounds__(256) k_attn2(const float* __restrict__ mask)
{
    extern __shared__ unsigned char dsm[];
    int K_len = g_maxlen;
    int q0 = blockIdx.x * QT; if (q0 >= K_len) return;
    int eb = blockIdx.y; int b = eb % Bdim;
    int tid = threadIdx.x, wid = tid >> 5;
    int rg = wid & 3, cg = wid >> 2;

    f16* Qh = (f16*)(dsm + AQ);
    f16* Kh = (f16*)(dsm + AKH);
    f16* Kl = (f16*)(dsm + AKL);
    float* Ssm = (float*)(dsm + AS);
    float* mt  = (float*)(dsm + AMT);
    f16* Ph = (f16*)(dsm + APH);      // pass-B alias over Q
    float* Ost = (float*)(dsm + AO);  // epilogue alias

    const size_t rowbase = (size_t)eb * KMAXd;

    {
        const f16* qh = g_qkvh + (rowbase + q0) * F3;
#pragma unroll
        for (int it = 0; it < 8; it++) {
            int idx = tid + it * 256;
            int r = idx >> 5, c8 = (idx & 31) * 8;
            *(uint4*)&Qh[r * QP + c8] = *(const uint4*)&qh[(size_t)r * F3 + c8];
        }
    }
    __syncthreads();

    int NT = (K_len + KT - 1) / KT;
    int rrow = tid >> 2, cbase = (tid & 3) * 8;
    float m_run = -3.0e38f;
    float* srow = g_S + ((size_t)eb * KMAXd + q0 + rrow) * KMAXd;

    // ---- pass A: S tiles -> gmem, row max in registers ----
    for (int kt = 0; kt < NT; kt++) {
        {
            const f16* kh = g_qkvh + (rowbase + (size_t)kt * KT) * F3 + 256;
            const f16* kl = g_qkvl + (rowbase + (size_t)kt * KT) * F3 + 256;
#pragma unroll
            for (int it = 0; it < 4; it++) {
                int idx = tid + it * 256;
                int r = idx >> 5, c8 = (idx & 31) * 8;
                *(uint4*)&Kh[r * KP + c8] = *(const uint4*)&kh[(size_t)r * F3 + c8];
                *(uint4*)&Kl[r * KP + c8] = *(const uint4*)&kl[(size_t)r * F3 + c8];
            }
        }
        if (tid < KT) {
            int k = kt * KT + tid;
            mt[tid] = (k < K_len)
                ? -1000000.0f * (1.0f - mask[b * Sdim + g_sid[eb * KMAXd + k]])
                : -1.0e30f;
        }
        __syncthreads();
        {
            wmma::fragment<wmma::accumulator, 16, 16, 16, float> sf;
            wmma::fill_fragment(sf, 0.f);
#pragma unroll
            for (int k16 = 0; k16 < 256; k16 += 16) {
                wmma::fragment<wmma::matrix_a, 16, 16, 16, half, wmma::row_major> ah;
                wmma::fragment<wmma::matrix_b, 16, 16, 16, half, wmma::col_major> bh, bl;
                wmma::load_matrix_sync(ah, &Qh[(rg * 16) * QP + k16], QP);
                wmma::load_matrix_sync(bh, &Kh[(cg * 16) * KP + k16], KP);
                wmma::load_matrix_sync(bl, &Kl[(cg * 16) * KP + k16], KP);
                wmma::mma_sync(sf, ah, bh, sf);
                wmma::mma_sync(sf, ah, bl, sf);
            }
            wmma::store_matrix_sync(&Ssm[(rg * 16) * SP + cg * 16], sf, SP,
                                    wmma::mem_row_major);
        }
        __syncthreads();
        {
            float sv[8]; float tmax = -3.0e38f;
#pragma unroll
            for (int i = 0; i < 8; i++) {
                sv[i] = Ssm[rrow * SP + cbase + i] * 0.0625f + mt[cbase + i];
                tmax = fmaxf(tmax, sv[i]);
            }
            tmax = fmaxf(tmax, __shfl_xor_sync(0xffffffffu, tmax, 1));
            tmax = fmaxf(tmax, __shfl_xor_sync(0xffffffffu, tmax, 2));
            m_run = fmaxf(m_run, tmax);
            *(float4*)&srow[kt * KT + cbase]     = make_float4(sv[0], sv[1], sv[2], sv[3]);
            *(float4*)&srow[kt * KT + cbase + 4] = make_float4(sv[4], sv[5], sv[6], sv[7]);
        }
        __syncthreads();
    }

    // ---- pass B: p = exp(s - m); l sum; O = P@V ----
    float l_run = 0.f;
    wmma::fragment<wmma::accumulator, 16, 16, 16, float> of[8];
#pragma unroll
    for (int j = 0; j < 8; j++) wmma::fill_fragment(of[j], 0.f);

    for (int kt = 0; kt < NT; kt++) {
        {
            float4 v0 = *(const float4*)&srow[kt * KT + cbase];
            float4 v1 = *(const float4*)&srow[kt * KT + cbase + 4];
            float pv[8] = {v0.x, v0.y, v0.z, v0.w, v1.x, v1.y, v1.z, v1.w};
            float ls = 0.f;
#pragma unroll
            for (int i = 0; i < 8; i++) { pv[i] = __expf(pv[i] - m_run); ls += pv[i]; }
            ls += __shfl_xor_sync(0xffffffffu, ls, 1);
            ls += __shfl_xor_sync(0xffffffffu, ls, 2);
            l_run += ls;
#pragma unroll
            for (int i = 0; i < 8; i += 2)
                *(__half2*)&Ph[rrow * PP + cbase + i] =
                    __floats2half2_rn(pv[i], pv[i + 1]);
        }
        {
            const f16* vh = g_qkvh + (rowbase + (size_t)kt * KT) * F3 + 512;
            const f16* vl = g_qkvl + (rowbase + (size_t)kt * KT) * F3 + 512;
#pragma unroll
            for (int it = 0; it < 4; it++) {
                int idx = tid + it * 256;
                int r = idx >> 5, c8 = (idx & 31) * 8;
                *(uint4*)&Kh[r * KP + c8] = *(const uint4*)&vh[(size_t)r * F3 + c8];
                *(uint4*)&Kl[r * KP + c8] = *(const uint4*)&vl[(size_t)r * F3 + c8];
            }
        }
        __syncthreads();
#pragma unroll
        for (int kk = 0; kk < KT; kk += 16) {
            wmma::fragment<wmma::matrix_a, 16, 16, 16, half, wmma::row_major> pah;
            wmma::load_matrix_sync(pah, &Ph[(rg * 16) * PP + kk], PP);
#pragma unroll
            for (int j = 0; j < 8; j++) {
                wmma::fragment<wmma::matrix_b, 16, 16, 16, half, wmma::row_major> vbh, vbl;
                wmma::load_matrix_sync(vbh, &Kh[kk * KP + cg * 128 + j * 16], KP);
                wmma::load_matrix_sync(vbl, &Kl[kk * KP + cg * 128 + j * 16], KP);
                wmma::mma_sync(of[j], pah, vbh, of[j]);
                wmma::mma_sync(of[j], pah, vbl, of[j]);
            }
        }
        __syncthreads();
    }

    // ---- epilogue ----
#pragma unroll
    for (int j = 0; j < 8; j++)
        wmma::store_matrix_sync(&Ost[(rg * 16) * OP + cg * 128 + j * 16], of[j], OP,
                                wmma::mem_row_major);
    __syncthreads();
    if (q0 + rrow < K_len) {
        float inv = 1.0f / l_run;
        size_t obase = (rowbase + q0 + rrow) * HDdim + (size_t)(tid & 3) * 64;
        int sbi = rrow * OP + (tid & 3) * 64;
#pragma unroll
        for (int c = 0; c < 64; c += 2)
            *(__half2*)&g_ctxh[obase + c] =
                __floats2half2_rn(Ost[sbi + c] * inv, Ost[sbi + c + 1] * inv);
    }
}

// ---------------- 6) FF GEMM + scatter-add ------------------------------------
__global__ void __launch_bounds__(256) k_ff(const float* __restrict__ bff,
                                            float* __restrict__ out)
{
    int K_len = g_maxlen;
    int row0 = blockIdx.y * 64; if (row0 >= K_len) return;
    int eb = blockIdx.z; int e = eb / Bdim, b = eb % Bdim;
    int col0 = blockIdx.x * 128;

    __shared__ __align__(16) unsigned char sraw[2 * GSTAGE];
    __shared__ int rows[64];
    __shared__ int scat[64];
    float* Cs = (float*)sraw;

    int tid = threadIdx.x;
    if (tid < 64) {
        int r = min(row0 + tid, K_len - 1);
        rows[tid] = r;
        scat[tid] = g_sid[eb * KMAXd + r];
    }
    __syncthreads();

    int wid = tid >> 5;
    int wr = wid >> 2, wc = wid & 3;

    wmma::fragment<wmma::accumulator, 16, 16, 16, float> acc[2][2];
#pragma unroll
    for (int i = 0; i < 2; i++)
#pragma unroll
        for (int j = 0; j < 2; j++) wmma::fill_fragment(acc[i][j], 0.f);

    const f16* Ag  = g_ctxh + (size_t)eb * KMAXd * HDdim;
    const f16* Bhg = g_Wfh + (size_t)e * HDdim * Ddim;
    const f16* Blg = g_Wfl + (size_t)e * HDdim * Ddim;
    const int T = HDdim / 32;

    g_issue(gstage(sraw, 0), tid, Ag, rows, HDdim, 0, Bhg, Blg, Ddim, col0);
    CP_COMMIT();
    for (int t = 0; t < T; t++) {
        if (t + 1 < T) {
            g_issue(gstage(sraw, (t + 1) & 1), tid, Ag, rows, HDdim, (t + 1) * 32,
                    Bhg, Blg, Ddim, col0);
            CP_COMMIT();
            CP_WAIT(1);
        } else {
            CP_WAIT(0);
        }
        __syncthreads();
        g_comp(gstage(sraw, t & 1), wr, wc, acc);
        __syncthreads();
    }

#pragma unroll
    for (int i = 0; i < 2; i++)
#pragma unroll
        for (int j = 0; j < 2; j++)
            wmma::store_matrix_sync(&Cs[(wr * 32 + i * 16) * CPITCH + wc * 32 + j * 16],
                                    acc[i][j], CPITCH, wmma::mem_row_major);
    __syncthreads();
    for (int idx = tid; idx < 64 * 128; idx += 256) {
        int r = idx >> 7, c = idx & 127;
        if (row0 + r < K_len) {
            atomicAdd(&out[((size_t)b * Sdim + scat[r]) * Ddim + col0 + c],
                      Cs[r * CPITCH + c] + bff[col0 + c]);
        }
    }
}

// ---------------- launch -----------------------------------------------------
extern "C" void kernel_launch(void* const* d_in, const int* in_sizes, int n_in,
                              void* d_out, int out_size)
{
    const float* X    = (const float*)d_in[0];
    const float* mask = (const float*)d_in[1];
    const float* wg   = (const float*)d_in[2];
    const float* bg   = (const float*)d_in[3];
    const float* Wqkv = (const float*)d_in[4];
    const float* bqkv = (const float*)d_in[5];
    const float* Wff  = (const float*)d_in[6];
    const float* bff  = (const float*)d_in[7];
    float* out = (float*)d_out;

    cudaFuncSetAttribute(k_attn2, cudaFuncAttributeMaxDynamicSharedMemorySize,
                         ATTN_SMEM);

    cudaMemsetAsync(out, 0, (size_t)out_size * sizeof(float));

    f16 *xh, *wqh, *wql, *wfh, *wfl;
    cudaGetSymbolAddress((void**)&xh, g_Xh);
    cudaGetSymbolAddress((void**)&wqh, g_Wqh); cudaGetSymbolAddress((void**)&wql, g_Wql);
    cudaGetSymbolAddress((void**)&wfh, g_Wfh); cudaGetSymbolAddress((void**)&wfl, g_Wfl);

    size_t nx  = (size_t)Bdim * Sdim * Ddim / 4;
    size_t nwq = (size_t)Edim * Ddim * F3 / 4;
    size_t nwf = (size_t)Edim * HDdim * Ddim / 4;
    k_cvtX<<<(unsigned)((nx  + 255) / 256), 256>>>(X, xh, nx);
    k_cvtW<<<(unsigned)((nwq + 255) / 256), 256>>>(Wqkv, wqh, wql, nwq);
    k_cvtW<<<(unsigned)((nwf + 255) / 256), 256>>>(Wff,  wfh, wfl, nwf);
    k_rtab<<<KMAXd, 512>>>();

    k_gate<<<Bdim * Sdim, 128>>>(X, wg, bg);
    k_reset<<<1, 1>>>();
    k_count<<<EB, 256>>>();
    k_build<<<EB, 256>>>();
    k_qkv<<<dim3(F3 / 128, Sdim / 64, EB), 256>>>(bqkv);
    k_attn2<<<dim3(Sdim / QT, EB), 256, ATTN_SMEM>>>(mask);
    k_ff<<<dim3(Ddim / 128, Sdim / 64, EB), 256>>>(bff, out);
}

// round 8
// speedup vs baseline: 4.6551x; 1.0387x over previous
#include <cuda_runtime.h>
#include <cuda_fp16.h>
#include <mma.h>
#include <math.h>
#include <stdint.h>

using namespace nvcuda;

#define Bdim  4
#define Sdim  2048
#define Ddim  2048
#define Edim  8
#define HDdim 256
#define F3    768
#define KMAXd 2048
#define EB    (Edim*Bdim)

typedef __half f16;

// ---------------- scratch (device globals; no allocations allowed) ----------
__device__ f16   g_qkvh[(size_t)EB * KMAXd * F3];  // post-rope [qf|kf|v] hi
__device__ f16   g_qkvl[(size_t)EB * KMAXd * F3];  // lo
__device__ float g_S[(size_t)EB * KMAXd * KMAXd];  // attention scores scratch
__device__ f16   g_ctxh[(size_t)EB * KMAXd * HDdim];
__device__ f16   g_Xh[(size_t)Bdim * Sdim * Ddim];
__device__ f16   g_Wqh[(size_t)Edim * Ddim * F3];
__device__ f16   g_Wql[(size_t)Edim * Ddim * F3];
__device__ f16   g_Wfh[(size_t)Edim * HDdim * Ddim];
__device__ f16   g_Wfl[(size_t)Edim * HDdim * Ddim];
__device__ float g_tcos[KMAXd * 512];
__device__ float g_tsin[KMAXd * 512];
__device__ int   g_sid[EB * KMAXd];
__device__ int   g_cnt[EB];
__device__ int   g_maxlen;
__device__ unsigned char g_emask[Bdim * Sdim];

// ---------------- cp.async helpers ------------------------------------------
__device__ __forceinline__ void cpa16(void* smem, const void* gmem)
{
    uint32_t s = (uint32_t)__cvta_generic_to_shared(smem);
    asm volatile("cp.async.cg.shared.global [%0], [%1], 16;\n" :: "r"(s), "l"(gmem));
}
#define CP_COMMIT() asm volatile("cp.async.commit_group;\n" ::: "memory")
#define CP_WAIT(n)  asm volatile("cp.async.wait_group %0;\n" :: "n"(n) : "memory")

// ---------------- 0b) fp32 -> fp16 hi/lo split (weights) ----------------------
__global__ void k_cvtW(const float* __restrict__ src, f16* __restrict__ h,
                       f16* __restrict__ l, size_t n4)
{
    size_t i = (size_t)blockIdx.x * blockDim.x + threadIdx.x;
    if (i >= n4) return;
    float4 v = reinterpret_cast<const float4*>(src)[i];
    __half2 h01 = __floats2half2_rn(v.x, v.y);
    __half2 h23 = __floats2half2_rn(v.z, v.w);
    float2 b01 = __half22float2(h01), b23 = __half22float2(h23);
    __half2 l01 = __floats2half2_rn(v.x - b01.x, v.y - b01.y);
    __half2 l23 = __floats2half2_rn(v.z - b23.x, v.w - b23.y);
    reinterpret_cast<uint2*>(h)[i] = make_uint2(*(uint32_t*)&h01, *(uint32_t*)&h23);
    reinterpret_cast<uint2*>(l)[i] = make_uint2(*(uint32_t*)&l01, *(uint32_t*)&l23);
}

// ---------------- 0c) rope tables (only K_len rows; fp32 sincos) -------------
__global__ void k_rtab()
{
    int k = blockIdx.x;
    if (k >= g_maxlen) return;
    int j = threadIdx.x;
    double freq = exp(((double)(-2 * j) / 1024.0) * log(10000.0));
    float ang = (float)k * (float)freq;
    float ss, cc;
    sincosf(ang, &ss, &cc);
    g_tcos[k * 512 + j] = cc;
    g_tsin[k * 512 + j] = ss;
}

// ---------------- 1) gate logits + top-2 mask + fused X->fp16 ----------------
__global__ void k_gate(const float* __restrict__ X,
                       const float* __restrict__ wg,
                       const float* __restrict__ bg,
                       f16* __restrict__ xh)
{
    int bs = blockIdx.x;
    const float* xr = X + (size_t)bs * Ddim;
    f16* xo = xh + (size_t)bs * Ddim;
    float acc[8];
#pragma unroll
    for (int e = 0; e < 8; e++) acc[e] = 0.f;
    for (int d = threadIdx.x; d < Ddim; d += 128) {
        float xv = xr[d];
        xo[d] = __float2half_rn(xv);
        const float4* w = (const float4*)(wg + d * Edim);
        float4 w0 = w[0], w1 = w[1];
        acc[0] = fmaf(xv, w0.x, acc[0]); acc[1] = fmaf(xv, w0.y, acc[1]);
        acc[2] = fmaf(xv, w0.z, acc[2]); acc[3] = fmaf(xv, w0.w, acc[3]);
        acc[4] = fmaf(xv, w1.x, acc[4]); acc[5] = fmaf(xv, w1.y, acc[5]);
        acc[6] = fmaf(xv, w1.z, acc[6]); acc[7] = fmaf(xv, w1.w, acc[7]);
    }
#pragma unroll
    for (int e = 0; e < 8; e++)
#pragma unroll
        for (int off = 16; off; off >>= 1)
            acc[e] += __shfl_down_sync(0xffffffffu, acc[e], off);

    __shared__ float red[4][8];
    int wid = threadIdx.x >> 5, lane = threadIdx.x & 31;
    if (lane == 0) {
#pragma unroll
        for (int e = 0; e < 8; e++) red[wid][e] = acc[e];
    }
    __syncthreads();
    if (threadIdx.x == 0) {
        float v[8];
#pragma unroll
        for (int e = 0; e < 8; e++)
            v[e] = red[0][e] + red[1][e] + red[2][e] + red[3][e] + bg[e];
        int e1 = 0; float b1 = v[0];
#pragma unroll
        for (int e = 1; e < 8; e++) if (v[e] > b1) { b1 = v[e]; e1 = e; }
        int e2 = -1; float b2 = -3.0e38f;
#pragma unroll
        for (int e = 0; e < 8; e++) if (e != e1 && v[e] > b2) { b2 = v[e]; e2 = e; }
        g_emask[bs] = (unsigned char)((1u << e1) | (1u << e2));
    }
}

__global__ void k_reset() { g_maxlen = 0; }

// ---------------- 2) per-(e,b) member counts + global max -------------------
__global__ void k_count()
{
    int eb = blockIdx.x; int e = eb / Bdim, b = eb % Bdim;
    int n = 0;
    for (int s = threadIdx.x; s < Sdim; s += 256)
        n += (g_emask[b * Sdim + s] >> e) & 1;
#pragma unroll
    for (int off = 16; off; off >>= 1) n += __shfl_down_sync(0xffffffffu, n, off);
    __shared__ int sm[8];
    int wid = threadIdx.x >> 5, lane = threadIdx.x & 31;
    if (lane == 0) sm[wid] = n;
    __syncthreads();
    if (threadIdx.x == 0) {
        int t = 0;
#pragma unroll
        for (int w = 0; w < 8; w++) t += sm[w];
        g_cnt[eb] = t;
        atomicMax(&g_maxlen, t);
    }
}

// ---------------- 3) build seq_ids ------------------------------------------
__global__ void k_build()
{
    int eb = blockIdx.x; int e = eb / Bdim, b = eb % Bdim;
    int pad = g_maxlen - g_cnt[eb];
    __shared__ int wsum[8];
    __shared__ int carry;
    if (threadIdx.x == 0) carry = 0;
    __syncthreads();
    int wid = threadIdx.x >> 5, lane = threadIdx.x & 31;
    for (int s0 = 0; s0 < Sdim; s0 += 256) {
        int s = s0 + threadIdx.x;
        int m = (g_emask[b * Sdim + s] >> e) & 1;
        unsigned bal = __ballot_sync(0xffffffffu, m);
        int mp_w = __popc(bal & ((1u << lane) - 1u));
        if (lane == 0) wsum[wid] = __popc(bal);
        __syncthreads();
        int pre = 0;
#pragma unroll
        for (int w = 0; w < 8; w++) if (w < wid) pre += wsum[w];
        int mp  = carry + pre + mp_w;
        int nmb = s - mp;
        bool sel = m || (nmb < pad);
        int pos  = mp + min(nmb, pad);
        if (sel) g_sid[eb * KMAXd + pos] = s;
        __syncthreads();
        if (threadIdx.x == 0) {
            int t = 0;
#pragma unroll
            for (int w = 0; w < 8; w++) t += wsum[w];
            carry += t;
        }
        __syncthreads();
    }
}

// ---------------- GEMM machinery: C[128 x 128], A fp16, B hi/lo, KT=32 -------
// stage: A@0 (128x40x2 = 10240) | Bh@10240 (8704) | Bl@18944 (8704) = 27648 B
#define APITCH 40
#define BPITCH 136
#define CPITCH 132
#define GSTAGE 27648
#define GEMM_DYNSM (128 * CPITCH * 4)   // 67584; >= 2*GSTAGE

struct GT { f16 *A, *Bh, *Bl; };
__device__ __forceinline__ GT gstage(unsigned char* base, int s)
{
    unsigned char* p = base + s * GSTAGE;
    GT t; t.A = (f16*)p; t.Bh = (f16*)(p + 10240); t.Bl = (f16*)(p + 18944);
    return t;
}

__device__ __forceinline__ void g_issue(
    GT t, int tid, const f16* __restrict__ Ag, const int* rows, int astr, int k0,
    const f16* __restrict__ Bhg, const f16* __restrict__ Blg, int bstr, int col0)
{
#pragma unroll
    for (int it = 0; it < 2; it++) {
        int idx = tid + it * 256;
        int row = idx >> 2, c8 = (idx & 3) * 8;
        cpa16(&t.A[row * APITCH + c8], Ag + (size_t)rows[row] * astr + k0 + c8);
    }
#pragma unroll
    for (int it = 0; it < 2; it++) {
        int idx = tid + it * 256;
        int row = idx >> 4, c8 = (idx & 15) * 8;
        size_t src = (size_t)(k0 + row) * bstr + col0 + c8;
        cpa16(&t.Bh[row * BPITCH + c8], Bhg + src);
        cpa16(&t.Bl[row * BPITCH + c8], Blg + src);
    }
}

// warp grid 4 rows x 2 cols; each warp computes 32 rows x 64 cols
__device__ __forceinline__ void g_comp(
    GT t, int wr, int wc,
    wmma::fragment<wmma::accumulator, 16, 16, 16, float> (&acc)[2][4])
{
#pragma unroll
    for (int kk = 0; kk < 32; kk += 16) {
        wmma::fragment<wmma::matrix_a, 16, 16, 16, half, wmma::row_major> a[2];
#pragma unroll
        for (int i = 0; i < 2; i++)
            wmma::load_matrix_sync(a[i], &t.A[(wr * 32 + i * 16) * APITCH + kk], APITCH);
#pragma unroll
        for (int j = 0; j < 4; j++) {
            wmma::fragment<wmma::matrix_b, 16, 16, 16, half, wmma::row_major> bh, bl;
            wmma::load_matrix_sync(bh, &t.Bh[kk * BPITCH + wc * 64 + j * 16], BPITCH);
            wmma::load_matrix_sync(bl, &t.Bl[kk * BPITCH + wc * 64 + j * 16], BPITCH);
#pragma unroll
            for (int i = 0; i < 2; i++) {
                wmma::mma_sync(acc[i][j], a[i], bh, acc[i][j]);
                wmma::mma_sync(acc[i][j], a[i], bl, acc[i][j]);
            }
        }
    }
}

// ---------------- 4) QKV GEMM + fused rope/split epilogue --------------------
__global__ void __launch_bounds__(256) k_qkv(const float* __restrict__ bq)
{
    extern __shared__ __align__(16) unsigned char sraw[];
    int K_len = g_maxlen;
    int row0 = blockIdx.y * 128; if (row0 >= K_len) return;
    int eb = blockIdx.z; int e = eb / Bdim, b = eb % Bdim;
    int col0 = blockIdx.x * 128;

    __shared__ int sids[128];
    float* Cs = (float*)sraw;

    int tid = threadIdx.x;
    if (tid < 128) sids[tid] = g_sid[eb * KMAXd + min(row0 + tid, K_len - 1)];
    __syncthreads();

    int wid = tid >> 5;
    int wr = wid >> 1, wc = wid & 1;

    wmma::fragment<wmma::accumulator, 16, 16, 16, float> acc[2][4];
#pragma unroll
    for (int i = 0; i < 2; i++)
#pragma unroll
        for (int j = 0; j < 4; j++) wmma::fill_fragment(acc[i][j], 0.f);

    const f16* Ag  = g_Xh + (size_t)b * Sdim * Ddim;
    const f16* Bhg = g_Wqh + (size_t)e * Ddim * F3;
    const f16* Blg = g_Wql + (size_t)e * Ddim * F3;
    const int T = Ddim / 32;

    g_issue(gstage(sraw, 0), tid, Ag, sids, Ddim, 0, Bhg, Blg, F3, col0);
    CP_COMMIT();
    for (int t = 0; t < T; t++) {
        if (t + 1 < T) {
            g_issue(gstage(sraw, (t + 1) & 1), tid, Ag, sids, Ddim, (t + 1) * 32,
                    Bhg, Blg, F3, col0);
            CP_COMMIT();
            CP_WAIT(1);
        } else {
            CP_WAIT(0);
        }
        __syncthreads();
        g_comp(gstage(sraw, t & 1), wr, wc, acc);
        __syncthreads();
    }

#pragma unroll
    for (int i = 0; i < 2; i++)
#pragma unroll
        for (int j = 0; j < 4; j++)
            wmma::store_matrix_sync(&Cs[(wr * 32 + i * 16) * CPITCH + wc * 64 + j * 16],
                                    acc[i][j], CPITCH, wmma::mem_row_major);
    __syncthreads();

    // fused: bias + rope + fp16 hi/lo split, with nope/pe half swap
    int blk = col0 >> 8;               // 0=q, 1=k, 2=v
    int halfsel = (col0 >> 7) & 1;     // for q/k: 0 = nope half, 1 = pe half
    int obase = blk * 256;
    const float* bqe = bq + e * F3 + col0;
    for (int idx = tid; idx < 128 * 64; idx += 256) {
        int r = idx >> 6, p = idx & 63;
        int grow = row0 + r;
        if (grow >= K_len) continue;
        float v0 = Cs[r * CPITCH + 2 * p]     + bqe[2 * p];
        float v1 = Cs[r * CPITCH + 2 * p + 1] + bqe[2 * p + 1];
        int outc;
        if (blk == 2) {
            outc = col0 + 2 * p;
        } else if (halfsel == 0) {
            outc = obase + 128 + 2 * p;
        } else {
            int ti = grow * 512 + e * 64 + p;
            float c = g_tcos[ti], s = g_tsin[ti];
            float r0 = v0 * c - v1 * s;
            float r1 = v0 * s + v1 * c;
            v0 = r0; v1 = r1;
            outc = obase + 2 * p;
        }
        size_t off = ((size_t)eb * KMAXd + grow) * F3 + outc;
        __half2 h2 = __floats2half2_rn(v0, v1);
        float2 back = __half22float2(h2);
        __half2 l2 = __floats2half2_rn(v0 - back.x, v1 - back.y);
        *(__half2*)&g_qkvh[off] = h2;
        *(__half2*)&g_qkvl[off] = l2;
    }
}

// ---------------- 5) attention (fp16 tensor-core, 2-pass softmax) -------------
#define QT 64
#define KT 32
#define QP 264
#define KP 264
#define SP 36
#define PP 40
#define OP 260
#define AQ   0
#define AKH  33792
#define AKL  50688
#define AS   67584
#define AMT  76800
#define APH  0
#define AO   5120
#define ATTN_SMEM 76928

__global__ void __launch_bounds__(256) k_attn2(const float* __restrict__ mask)
{
    extern __shared__ unsigned char dsm[];
    int K_len = g_maxlen;
    int q0 = blockIdx.x * QT; if (q0 >= K_len) return;
    int eb = blockIdx.y; int b = eb % Bdim;
    int tid = threadIdx.x, wid = tid >> 5;
    int rg = wid & 3, cg = wid >> 2;

    f16* Qh = (f16*)(dsm + AQ);
    f16* Kh = (f16*)(dsm + AKH);
    f16* Kl = (f16*)(dsm + AKL);
    float* Ssm = (float*)(dsm + AS);
    float* mt  = (float*)(dsm + AMT);
    f16* Ph = (f16*)(dsm + APH);
    float* Ost = (float*)(dsm + AO);

    const size_t rowbase = (size_t)eb * KMAXd;

    {
        const f16* qh = g_qkvh + (rowbase + q0) * F3;
#pragma unroll
        for (int it = 0; it < 8; it++) {
            int idx = tid + it * 256;
            int r = idx >> 5, c8 = (idx & 31) * 8;
            *(uint4*)&Qh[r * QP + c8] = *(const uint4*)&qh[(size_t)r * F3 + c8];
        }
    }
    __syncthreads();

    int NT = (K_len + KT - 1) / KT;
    int rrow = tid >> 2, cbase = (tid & 3) * 8;
    float m_run = -3.0e38f;
    float* srow = g_S + ((size_t)eb * KMAXd + q0 + rrow) * KMAXd;

    for (int kt = 0; kt < NT; kt++) {
        {
            const f16* kh = g_qkvh + (rowbase + (size_t)kt * KT) * F3 + 256;
            const f16* kl = g_qkvl + (rowbase + (size_t)kt * KT) * F3 + 256;
#pragma unroll
            for (int it = 0; it < 4; it++) {
                int idx = tid + it * 256;
                int r = idx >> 5, c8 = (idx & 31) * 8;
                *(uint4*)&Kh[r * KP + c8] = *(const uint4*)&kh[(size_t)r * F3 + c8];
                *(uint4*)&Kl[r * KP + c8] = *(const uint4*)&kl[(size_t)r * F3 + c8];
            }
        }
        if (tid < KT) {
            int k = kt * KT + tid;
            mt[tid] = (k < K_len)
                ? -1000000.0f * (1.0f - mask[b * Sdim + g_sid[eb * KMAXd + k]])
                : -1.0e30f;
        }
        __syncthreads();
        {
            wmma::fragment<wmma::accumulator, 16, 16, 16, float> sf;
            wmma::fill_fragment(sf, 0.f);
#pragma unroll
            for (int k16 = 0; k16 < 256; k16 += 16) {
                wmma::fragment<wmma::matrix_a, 16, 16, 16, half, wmma::row_major> ah;
                wmma::fragment<wmma::matrix_b, 16, 16, 16, half, wmma::col_major> bh, bl;
                wmma::load_matrix_sync(ah, &Qh[(rg * 16) * QP + k16], QP);
                wmma::load_matrix_sync(bh, &Kh[(cg * 16) * KP + k16], KP);
                wmma::load_matrix_sync(bl, &Kl[(cg * 16) * KP + k16], KP);
                wmma::mma_sync(sf, ah, bh, sf);
                wmma::mma_sync(sf, ah, bl, sf);
            }
            wmma::store_matrix_sync(&Ssm[(rg * 16) * SP + cg * 16], sf, SP,
                                    wmma::mem_row_major);
        }
        __syncthreads();
        {
            float sv[8]; float tmax = -3.0e38f;
#pragma unroll
            for (int i = 0; i < 8; i++) {
                sv[i] = Ssm[rrow * SP + cbase + i] * 0.0625f + mt[cbase + i];
                tmax = fmaxf(tmax, sv[i]);
            }
            tmax = fmaxf(tmax, __shfl_xor_sync(0xffffffffu, tmax, 1));
            tmax = fmaxf(tmax, __shfl_xor_sync(0xffffffffu, tmax, 2));
            m_run = fmaxf(m_run, tmax);
            *(float4*)&srow[kt * KT + cbase]     = make_float4(sv[0], sv[1], sv[2], sv[3]);
            *(float4*)&srow[kt * KT + cbase + 4] = make_float4(sv[4], sv[5], sv[6], sv[7]);
        }
        __syncthreads();
    }

    float l_run = 0.f;
    wmma::fragment<wmma::accumulator, 16, 16, 16, float> of[8];
#pragma unroll
    for (int j = 0; j < 8; j++) wmma::fill_fragment(of[j], 0.f);

    for (int kt = 0; kt < NT; kt++) {
        {
            float4 v0 = *(const float4*)&srow[kt * KT + cbase];
            float4 v1 = *(const float4*)&srow[kt * KT + cbase + 4];
            float pv[8] = {v0.x, v0.y, v0.z, v0.w, v1.x, v1.y, v1.z, v1.w};
            float ls = 0.f;
#pragma unroll
            for (int i = 0; i < 8; i++) { pv[i] = __expf(pv[i] - m_run); ls += pv[i]; }
            ls += __shfl_xor_sync(0xffffffffu, ls, 1);
            ls += __shfl_xor_sync(0xffffffffu, ls, 2);
            l_run += ls;
#pragma unroll
            for (int i = 0; i < 8; i += 2)
                *(__half2*)&Ph[rrow * PP + cbase + i] =
                    __floats2half2_rn(pv[i], pv[i + 1]);
        }
        {
            const f16* vh = g_qkvh + (rowbase + (size_t)kt * KT) * F3 + 512;
            const f16* vl = g_qkvl + (rowbase + (size_t)kt * KT) * F3 + 512;
#pragma unroll
            for (int it = 0; it < 4; it++) {
                int idx = tid + it * 256;
                int r = idx >> 5, c8 = (idx & 31) * 8;
                *(uint4*)&Kh[r * KP + c8] = *(const uint4*)&vh[(size_t)r * F3 + c8];
                *(uint4*)&Kl[r * KP + c8] = *(const uint4*)&vl[(size_t)r * F3 + c8];
            }
        }
        __syncthreads();
#pragma unroll
        for (int kk = 0; kk < KT; kk += 16) {
            wmma::fragment<wmma::matrix_a, 16, 16, 16, half, wmma::row_major> pah;
            wmma::load_matrix_sync(pah, &Ph[(rg * 16) * PP + kk], PP);
#pragma unroll
            for (int j = 0; j < 8; j++) {
                wmma::fragment<wmma::matrix_b, 16, 16, 16, half, wmma::row_major> vbh, vbl;
                wmma::load_matrix_sync(vbh, &Kh[kk * KP + cg * 128 + j * 16], KP);
                wmma::load_matrix_sync(vbl, &Kl[kk * KP + cg * 128 + j * 16], KP);
                wmma::mma_sync(of[j], pah, vbh, of[j]);
                wmma::mma_sync(of[j], pah, vbl, of[j]);
            }
        }
        __syncthreads();
    }

#pragma unroll
    for (int j = 0; j < 8; j++)
        wmma::store_matrix_sync(&Ost[(rg * 16) * OP + cg * 128 + j * 16], of[j], OP,
                                wmma::mem_row_major);
    __syncthreads();
    if (q0 + rrow < K_len) {
        float inv = 1.0f / l_run;
        size_t obase = (rowbase + q0 + rrow) * HDdim + (size_t)(tid & 3) * 64;
        int sbi = rrow * OP + (tid & 3) * 64;
#pragma unroll
        for (int c = 0; c < 64; c += 2)
            *(__half2*)&g_ctxh[obase + c] =
                __floats2half2_rn(Ost[sbi + c] * inv, Ost[sbi + c + 1] * inv);
    }
}

// ---------------- 6) FF GEMM + scatter-add ------------------------------------
__global__ void __launch_bounds__(256) k_ff(const float* __restrict__ bff,
                                            float* __restrict__ out)
{
    extern __shared__ __align__(16) unsigned char sraw[];
    int K_len = g_maxlen;
    int row0 = blockIdx.y * 128; if (row0 >= K_len) return;
    int eb = blockIdx.z; int e = eb / Bdim, b = eb % Bdim;
    int col0 = blockIdx.x * 128;

    __shared__ int rows[128];
    __shared__ int scat[128];
    float* Cs = (float*)sraw;

    int tid = threadIdx.x;
    if (tid < 128) {
        int r = min(row0 + tid, K_len - 1);
        rows[tid] = r;
        scat[tid] = g_sid[eb * KMAXd + r];
    }
    __syncthreads();

    int wid = tid >> 5;
    int wr = wid >> 1, wc = wid & 1;

    wmma::fragment<wmma::accumulator, 16, 16, 16, float> acc[2][4];
#pragma unroll
    for (int i = 0; i < 2; i++)
#pragma unroll
        for (int j = 0; j < 4; j++) wmma::fill_fragment(acc[i][j], 0.f);

    const f16* Ag  = g_ctxh + (size_t)eb * KMAXd * HDdim;
    const f16* Bhg = g_Wfh + (size_t)e * HDdim * Ddim;
    const f16* Blg = g_Wfl + (size_t)e * HDdim * Ddim;
    const int T = HDdim / 32;

    g_issue(gstage(sraw, 0), tid, Ag, rows, HDdim, 0, Bhg, Blg, Ddim, col0);
    CP_COMMIT();
    for (int t = 0; t < T; t++) {
        if (t + 1 < T) {
            g_issue(gstage(sraw, (t + 1) & 1), tid, Ag, rows, HDdim, (t + 1) * 32,
                    Bhg, Blg, Ddim, col0);
            CP_COMMIT();
            CP_WAIT(1);
        } else {
            CP_WAIT(0);
        }
        __syncthreads();
        g_comp(gstage(sraw, t & 1), wr, wc, acc);
        __syncthreads();
    }

#pragma unroll
    for (int i = 0; i < 2; i++)
#pragma unroll
        for (int j = 0; j < 4; j++)
            wmma::store_matrix_sync(&Cs[(wr * 32 + i * 16) * CPITCH + wc * 64 + j * 16],
                                    acc[i][j], CPITCH, wmma::mem_row_major);
    __syncthreads();
    for (int idx = tid; idx < 128 * 128; idx += 256) {
        int r = idx >> 7, c = idx & 127;
        if (row0 + r < K_len) {
            atomicAdd(&out[((size_t)b * Sdim + scat[r]) * Ddim + col0 + c],
                      Cs[r * CPITCH + c] + bff[col0 + c]);
        }
    }
}

// ---------------- launch -----------------------------------------------------
extern "C" void kernel_launch(void* const* d_in, const int* in_sizes, int n_in,
                              void* d_out, int out_size)
{
    const float* X    = (const float*)d_in[0];
    const float* mask = (const float*)d_in[1];
    const float* wg   = (const float*)d_in[2];
    const float* bg   = (const float*)d_in[3];
    const float* Wqkv = (const float*)d_in[4];
    const float* bqkv = (const float*)d_in[5];
    const float* Wff  = (const float*)d_in[6];
    const float* bff  = (const float*)d_in[7];
    float* out = (float*)d_out;

    cudaFuncSetAttribute(k_attn2, cudaFuncAttributeMaxDynamicSharedMemorySize,
                         ATTN_SMEM);
    cudaFuncSetAttribute(k_qkv, cudaFuncAttributeMaxDynamicSharedMemorySize,
                         GEMM_DYNSM);
    cudaFuncSetAttribute(k_ff, cudaFuncAttributeMaxDynamicSharedMemorySize,
                         GEMM_DYNSM);

    cudaMemsetAsync(out, 0, (size_t)out_size * sizeof(float));

    f16 *xh, *wqh, *wql, *wfh, *wfl;
    cudaGetSymbolAddress((void**)&xh, g_Xh);
    cudaGetSymbolAddress((void**)&wqh, g_Wqh); cudaGetSymbolAddress((void**)&wql, g_Wql);
    cudaGetSymbolAddress((void**)&wfh, g_Wfh); cudaGetSymbolAddress((void**)&wfl, g_Wfl);

    size_t nwq = (size_t)Edim * Ddim * F3 / 4;
    size_t nwf = (size_t)Edim * HDdim * Ddim / 4;
    k_cvtW<<<(unsigned)((nwq + 255) / 256), 256>>>(Wqkv, wqh, wql, nwq);
    k_cvtW<<<(unsigned)((nwf + 255) / 256), 256>>>(Wff,  wfh, wfl, nwf);

    k_gate<<<Bdim * Sdim, 128>>>(X, wg, bg, xh);
    k_reset<<<1, 1>>>();
    k_count<<<EB, 256>>>();
    k_build<<<EB, 256>>>();
    k_rtab<<<KMAXd, 512>>>();
    k_qkv<<<dim3(F3 / 128, Sdim / 128, EB), 256, GEMM_DYNSM>>>(bqkv);
    k_attn2<<<dim3(Sdim / QT, EB), 256, ATTN_SMEM>>>(mask);
    k_ff<<<dim3(Ddim / 128, Sdim / 128, EB), 256, GEMM_DYNSM>>>(bff, out);
}